// round 4
// baseline (speedup 1.0000x reference)
#include <cuda_runtime.h>
#include <cstdint>

// Problem constants (fixed shapes for GCN_8967891714538)
#define N_NODES 50000
#define N_EDGES 800000
#define IN_CH   128
#define HID_CH  128
#define OUT_CH  64

#define CHUNK   1024
#define NCHUNKS ((N_NODES + CHUNK - 1) / CHUNK)   // 49

// ---------------- scratch (static device globals; no allocation) -------------
__device__ __align__(16) float g_hs1[(size_t)N_NODES * HID_CH];  // (x @ W1) * dinv[row]
__device__ __align__(16) float g_a1 [(size_t)N_NODES * HID_CH];  // relu(agg1 + b1)
__device__ __align__(16) float g_hs2[(size_t)N_NODES * OUT_CH];  // (a1 @ W2) * dinv[row]
__device__ __align__(16) float g_w1t[IN_CH  * HID_CH];           // W1^T  [C][K]
__device__ __align__(16) float g_w2t[HID_CH * OUT_CH];           // W2^T  [C][K]
__device__ float g_dinv[N_NODES];
__device__ int   g_ecnt[N_NODES];
__device__ int   g_fill[N_NODES];
__device__ int   g_rowptr[N_NODES + 1];
__device__ int   g_esrc[N_EDGES];
__device__ int   g_csum[NCHUNKS];
__device__ int   g_is64;   // 1 if edge_index buffer is int64, 0 if int32

// ---------------- edge_index dtype detection ---------------------------------
// Genuine int64 node ids are in [0, N_NODES). If the buffer is really int32,
// a long-long read packs two random ids (lo | hi<<32) >= 2^32 almost surely.
__device__ __forceinline__ int edge_at(const void* __restrict__ ei, int idx) {
    if (g_is64) return (int)((const long long*)ei)[idx];
    return ((const int*)ei)[idx];
}

// ---------------- prep: detect + init counters + transpose W1/W2 --------------
__global__ void k_prep(const void* __restrict__ ei,
                       const float* __restrict__ W1,
                       const float* __restrict__ W2) {
    int gtid = blockIdx.x * blockDim.x + threadIdx.x;
    int nthr = gridDim.x * blockDim.x;

    if (gtid == 0) {
        const long long* p = (const long long*)ei;
        int is64 = 1;
        for (int i = 0; i < 64; i++) {           // 512 bytes — safe for both layouts
            long long v = p[i];
            if (v < 0 || v >= (long long)N_NODES) { is64 = 0; break; }
        }
        g_is64 = is64;
    }
    for (int v = gtid; v < N_NODES; v += nthr) { g_ecnt[v] = 0; g_fill[v] = 0; }
    // W1t[c*K + k] = W1[k*C + c], K = IN_CH, C = HID_CH
    for (int i = gtid; i < IN_CH * HID_CH; i += nthr) {
        int c = i / IN_CH, k = i % IN_CH;
        g_w1t[i] = W1[k * HID_CH + c];
    }
    // W2t[c*K + k] = W2[k*C + c], K = HID_CH, C = OUT_CH
    for (int i = gtid; i < HID_CH * OUT_CH; i += nthr) {
        int c = i / HID_CH, k = i % HID_CH;
        g_w2t[i] = W2[k * OUT_CH + c];
    }
}

// ---------------- CSR build ---------------------------------------------------
__global__ void k_count(const void* __restrict__ ei) {
    int e = blockIdx.x * blockDim.x + threadIdx.x;
    if (e < N_EDGES) {
        int d = edge_at(ei, N_EDGES + e);
        atomicAdd(&g_ecnt[d], 1);
    }
}

__global__ void k_chunksum() {
    __shared__ int sdata[256];
    int c = blockIdx.x, t = threadIdx.x;
    int base = c * CHUNK;
    int s = 0;
    for (int i = t; i < CHUNK; i += 256) {
        int v = base + i;
        s += (v < N_NODES) ? g_ecnt[v] : 0;
    }
    sdata[t] = s;
    __syncthreads();
    for (int off = 128; off > 0; off >>= 1) {
        if (t < off) sdata[t] += sdata[t + off];
        __syncthreads();
    }
    if (t == 0) g_csum[c] = sdata[0];
}

// chunk-local scan + global offset + dinv, all in one kernel (49 blocks x 1024)
__global__ void k_scanfinal() {
    __shared__ int s[CHUNK];
    __shared__ int base;
    int c = blockIdx.x, t = threadIdx.x;
    if (t == 0) {
        int run = 0;
        for (int i = 0; i < c; i++) run += g_csum[i];
        base = run;
    }
    int v = c * CHUNK + t;
    int cnt = (v < N_NODES) ? g_ecnt[v] : 0;
    s[t] = cnt;
    __syncthreads();
    // Hillis-Steele inclusive scan
    for (int off = 1; off < CHUNK; off <<= 1) {
        int val = (t >= off) ? s[t - off] : 0;
        __syncthreads();
        s[t] += val;
        __syncthreads();
    }
    if (v < N_NODES) {
        g_rowptr[v] = base + s[t] - cnt;           // exclusive
        g_dinv[v]   = rsqrtf((float)(cnt + 1));    // +1 self-loop
    }
    if (c == NCHUNKS - 1 && t == 0) {
        int last = N_NODES - c * CHUNK - 1;        // last valid index in this chunk
        g_rowptr[N_NODES] = base + s[last];
    }
}

__global__ void k_fill(const void* __restrict__ ei) {
    int e = blockIdx.x * blockDim.x + threadIdx.x;
    if (e < N_EDGES) {
        int sN = edge_at(ei, e);
        int d  = edge_at(ei, N_EDGES + e);
        int pos = g_rowptr[d] + atomicAdd(&g_fill[d], 1);
        g_esrc[pos] = sN;
    }
}

// ---------------- smem-tiled register-blocked GEMM ----------------------------
// Block: 256 threads computes [R=32 rows x C cols]. X tile staged in smem.
// Thread (tx,ty): cols 4*tx..4*tx+3, rows ty*RPT..ty*RPT+RPT-1.
// Per 4-k chunk: 4 LDG.128 (Wt, L1-resident) + RPT LDS.128 (broadcast) for
// RPT*16 FMAs. Epilogue scales rows by dinv.
template<int K, int C>
__device__ __forceinline__ void gemm_body(const float* __restrict__ X,
                                          const float* __restrict__ Wt,
                                          float* __restrict__ out) {
    constexpr int R   = 32;
    constexpr int CT  = C / 4;        // col-threads
    constexpr int RT  = 256 / CT;     // row-threads
    constexpr int RPT = R / RT;       // rows per thread

    __shared__ float sx[R * K];       // 16 KB

    const int tid  = threadIdx.x;
    const int row0 = blockIdx.x * R;

    // stage X tile (guard tail rows)
#pragma unroll
    for (int j = 0; j < (R * K / 4) / 256; j++) {
        int idx  = j * 256 + tid;             // float4 index in tile
        int r    = idx / (K / 4);
        int grow = row0 + r;
        float4 v = make_float4(0.f, 0.f, 0.f, 0.f);
        if (grow < N_NODES) v = __ldg((const float4*)(X + (size_t)grow * K) + (idx % (K / 4)));
        ((float4*)sx)[idx] = v;
    }
    __syncthreads();

    const int tx = tid % CT;
    const int ty = tid / CT;
    const int col0  = tx * 4;
    const int rbase = ty * RPT;

    float acc[RPT][4];
#pragma unroll
    for (int r = 0; r < RPT; r++)
#pragma unroll
        for (int c = 0; c < 4; c++) acc[r][c] = 0.f;

    const float4* w0p = (const float4*)(Wt + (size_t)(col0 + 0) * K);
    const float4* w1p = (const float4*)(Wt + (size_t)(col0 + 1) * K);
    const float4* w2p = (const float4*)(Wt + (size_t)(col0 + 2) * K);
    const float4* w3p = (const float4*)(Wt + (size_t)(col0 + 3) * K);

#pragma unroll 4
    for (int kc = 0; kc < K / 4; kc++) {
        float4 w0 = __ldg(&w0p[kc]);
        float4 w1 = __ldg(&w1p[kc]);
        float4 w2 = __ldg(&w2p[kc]);
        float4 w3 = __ldg(&w3p[kc]);
#pragma unroll
        for (int r = 0; r < RPT; r++) {
            float4 xv = *(const float4*)(sx + (rbase + r) * K + kc * 4);
            acc[r][0] = fmaf(xv.x, w0.x, acc[r][0]);
            acc[r][0] = fmaf(xv.y, w0.y, acc[r][0]);
            acc[r][0] = fmaf(xv.z, w0.z, acc[r][0]);
            acc[r][0] = fmaf(xv.w, w0.w, acc[r][0]);
            acc[r][1] = fmaf(xv.x, w1.x, acc[r][1]);
            acc[r][1] = fmaf(xv.y, w1.y, acc[r][1]);
            acc[r][1] = fmaf(xv.z, w1.z, acc[r][1]);
            acc[r][1] = fmaf(xv.w, w1.w, acc[r][1]);
            acc[r][2] = fmaf(xv.x, w2.x, acc[r][2]);
            acc[r][2] = fmaf(xv.y, w2.y, acc[r][2]);
            acc[r][2] = fmaf(xv.z, w2.z, acc[r][2]);
            acc[r][2] = fmaf(xv.w, w2.w, acc[r][2]);
            acc[r][3] = fmaf(xv.x, w3.x, acc[r][3]);
            acc[r][3] = fmaf(xv.y, w3.y, acc[r][3]);
            acc[r][3] = fmaf(xv.z, w3.z, acc[r][3]);
            acc[r][3] = fmaf(xv.w, w3.w, acc[r][3]);
        }
    }

#pragma unroll
    for (int r = 0; r < RPT; r++) {
        int row = row0 + rbase + r;
        if (row < N_NODES) {
            float s = g_dinv[row];
            float4 o = make_float4(acc[r][0] * s, acc[r][1] * s,
                                   acc[r][2] * s, acc[r][3] * s);
            *(float4*)(out + (size_t)row * C + col0) = o;
        }
    }
}

__global__ void __launch_bounds__(256) k_gemm1(const float* __restrict__ X) {
    gemm_body<IN_CH, HID_CH>(X, g_w1t, g_hs1);
}
__global__ void __launch_bounds__(256) k_gemm2() {
    gemm_body<HID_CH, OUT_CH>(g_a1, g_w2t, g_hs2);
}

// ---------------- CSR gather aggregation -------------------------------------
// out[v] = (hs[v] + sum_{s in in(v)} hs[s]) * dinv[v] + bias  [+ relu]
template<int C, bool RELU>
__device__ __forceinline__ void agg_body(const float* __restrict__ hs,
                                         const float* __restrict__ bias,
                                         float* __restrict__ out) {
    constexpr int F4 = C / 4;   // float4 lanes per node row
    int gtid = blockIdx.x * blockDim.x + threadIdx.x;
    int node = gtid / F4;
    int j    = gtid % F4;
    if (node >= N_NODES) return;

    const float4* hv = (const float4*)hs;
    float4 acc0 = __ldg(&hv[(size_t)node * F4 + j]);   // self-loop term (pre-scaled)
    float4 acc1 = make_float4(0.f, 0.f, 0.f, 0.f);

    int beg = g_rowptr[node];
    int end = g_rowptr[node + 1];
    int e = beg;
    for (; e + 2 <= end; e += 2) {
        int s0 = g_esrc[e];
        int s1 = g_esrc[e + 1];
        float4 v0 = __ldg(&hv[(size_t)s0 * F4 + j]);
        float4 v1 = __ldg(&hv[(size_t)s1 * F4 + j]);
        acc0.x += v0.x; acc0.y += v0.y; acc0.z += v0.z; acc0.w += v0.w;
        acc1.x += v1.x; acc1.y += v1.y; acc1.z += v1.z; acc1.w += v1.w;
    }
    if (e < end) {
        int s0 = g_esrc[e];
        float4 v0 = __ldg(&hv[(size_t)s0 * F4 + j]);
        acc0.x += v0.x; acc0.y += v0.y; acc0.z += v0.z; acc0.w += v0.w;
    }
    acc0.x += acc1.x; acc0.y += acc1.y; acc0.z += acc1.z; acc0.w += acc1.w;

    float dv = g_dinv[node];
    float4 b = __ldg(&((const float4*)bias)[j]);
    float4 r;
    r.x = fmaf(acc0.x, dv, b.x);
    r.y = fmaf(acc0.y, dv, b.y);
    r.z = fmaf(acc0.z, dv, b.z);
    r.w = fmaf(acc0.w, dv, b.w);
    if (RELU) {
        r.x = fmaxf(r.x, 0.0f); r.y = fmaxf(r.y, 0.0f);
        r.z = fmaxf(r.z, 0.0f); r.w = fmaxf(r.w, 0.0f);
    }
    ((float4*)out)[(size_t)node * F4 + j] = r;
}

__global__ void k_agg1(const float* __restrict__ b1) {
    agg_body<HID_CH, true>(g_hs1, b1, g_a1);
}
__global__ void k_agg2(const float* __restrict__ b2, float* __restrict__ out) {
    agg_body<OUT_CH, false>(g_hs2, b2, out);
}

// ---------------- launch ------------------------------------------------------
extern "C" void kernel_launch(void* const* d_in, const int* in_sizes, int n_in,
                              void* d_out, int out_size) {
    const float* x  = (const float*)d_in[0];
    const void*  ei = d_in[1];
    const float* W1 = (const float*)d_in[2];
    const float* b1 = (const float*)d_in[3];
    const float* W2 = (const float*)d_in[4];
    const float* b2 = (const float*)d_in[5];
    float* out = (float*)d_out;
    (void)in_sizes; (void)n_in; (void)out_size;

    const int TB = 256;
    const int GEMM_R = 32;
    const int GBLKS  = (N_NODES + GEMM_R - 1) / GEMM_R;

    // #1 prep: dtype detect + counter init + W transposes
    k_prep     <<<256, TB>>>(ei, W1, W2);
    // #2..#5 CSR build (+ dinv fused into the scan)
    k_count    <<<(N_EDGES + TB - 1) / TB, TB>>>(ei);
    k_chunksum <<<NCHUNKS, 256>>>();
    k_scanfinal<<<NCHUNKS, CHUNK>>>();
    k_fill     <<<(N_EDGES + TB - 1) / TB, TB>>>(ei);

    // #6 Layer 1 GEMM: hs1 = (x @ W1) * dinv
    k_gemm1<<<GBLKS, 256>>>(x);
    // #7 a1 = relu(gather(hs1)*dinv + b1)
    k_agg1<<<N_NODES * (HID_CH / 4) / TB, TB>>>(b1);

    // #8 Layer 2 GEMM: hs2 = (a1 @ W2) * dinv
    k_gemm2<<<GBLKS, 256>>>();
    // #9 out = gather(hs2)*dinv + b2
    k_agg2<<<N_NODES * (OUT_CH / 4) / TB, TB>>>(b2, out);
}

// round 5
// speedup vs baseline: 1.6960x; 1.6960x over previous
#include <cuda_runtime.h>
#include <cstdint>

// Problem constants (fixed shapes for GCN_8967891714538)
#define N_NODES 50000
#define N_EDGES 800000
#define IN_CH   128
#define HID_CH  128
#define OUT_CH  64

#define CHUNK   1024
#define NCHUNKS ((N_NODES + CHUNK - 1) / CHUNK)   // 49

// ---------------- scratch (static device globals; no allocation) -------------
__device__ __align__(16) float g_h1 [(size_t)N_NODES * HID_CH];  // x @ W1 (unscaled)
__device__ __align__(16) float g_a1 [(size_t)N_NODES * HID_CH];  // relu(agg1 + b1)
__device__ __align__(16) float g_h2 [(size_t)N_NODES * OUT_CH];  // a1 @ W2 (unscaled)
__device__ float g_dinv[N_NODES];
__device__ int   g_ecnt[N_NODES];
__device__ int   g_fill[N_NODES];
__device__ int   g_rowptr[N_NODES + 1];
__device__ int   g_esrc[N_EDGES];
__device__ int   g_csum[NCHUNKS];
__device__ int   g_is64;   // 1 if edge_index buffer is int64, 0 if int32

// ---------------- edge_index dtype detection ---------------------------------
// Genuine int64 node ids are in [0, N_NODES). If the buffer is really int32,
// a long-long read packs two random ids (lo | hi<<32) >= 2^32 almost surely.
__device__ __forceinline__ int edge_at(const void* __restrict__ ei, int idx) {
    if (g_is64) return (int)((const long long*)ei)[idx];
    return ((const int*)ei)[idx];
}

// ---------------- prep: detect + init counters --------------------------------
__global__ void k_prep(const void* __restrict__ ei) {
    int gtid = blockIdx.x * blockDim.x + threadIdx.x;
    int nthr = gridDim.x * blockDim.x;

    if (gtid == 0) {
        const long long* p = (const long long*)ei;
        int is64 = 1;
        for (int i = 0; i < 64; i++) {           // 512 bytes — safe for both layouts
            long long v = p[i];
            if (v < 0 || v >= (long long)N_NODES) { is64 = 0; break; }
        }
        g_is64 = is64;
    }
    for (int v = gtid; v < N_NODES; v += nthr) { g_ecnt[v] = 0; g_fill[v] = 0; }
}

// ---------------- CSR build ---------------------------------------------------
__global__ void k_count(const void* __restrict__ ei) {
    int e = blockIdx.x * blockDim.x + threadIdx.x;
    if (e < N_EDGES) {
        int d = edge_at(ei, N_EDGES + e);
        atomicAdd(&g_ecnt[d], 1);
    }
}

__global__ void k_chunksum() {
    __shared__ int sdata[256];
    int c = blockIdx.x, t = threadIdx.x;
    int base = c * CHUNK;
    int s = 0;
    for (int i = t; i < CHUNK; i += 256) {
        int v = base + i;
        s += (v < N_NODES) ? g_ecnt[v] : 0;
    }
    sdata[t] = s;
    __syncthreads();
    for (int off = 128; off > 0; off >>= 1) {
        if (t < off) sdata[t] += sdata[t + off];
        __syncthreads();
    }
    if (t == 0) g_csum[c] = sdata[0];
}

// chunk-local scan + global offset + dinv, all in one kernel (49 blocks x 1024)
__global__ void k_scanfinal() {
    __shared__ int s[CHUNK];
    __shared__ int base;
    int c = blockIdx.x, t = threadIdx.x;
    if (t == 0) {
        int run = 0;
        for (int i = 0; i < c; i++) run += g_csum[i];
        base = run;
    }
    int v = c * CHUNK + t;
    int cnt = (v < N_NODES) ? g_ecnt[v] : 0;
    s[t] = cnt;
    __syncthreads();
    // Hillis-Steele inclusive scan
    for (int off = 1; off < CHUNK; off <<= 1) {
        int val = (t >= off) ? s[t - off] : 0;
        __syncthreads();
        s[t] += val;
        __syncthreads();
    }
    if (v < N_NODES) {
        g_rowptr[v] = base + s[t] - cnt;           // exclusive
        g_dinv[v]   = rsqrtf((float)(cnt + 1));    // +1 self-loop
    }
    if (c == NCHUNKS - 1 && t == 0) {
        int last = N_NODES - c * CHUNK - 1;        // last valid index in this chunk
        g_rowptr[N_NODES] = base + s[last];
    }
}

__global__ void k_fill(const void* __restrict__ ei) {
    int e = blockIdx.x * blockDim.x + threadIdx.x;
    if (e < N_EDGES) {
        int sN = edge_at(ei, e);
        int d  = edge_at(ei, N_EDGES + e);
        int pos = g_rowptr[d] + atomicAdd(&g_fill[d], 1);
        g_esrc[pos] = sN;
    }
}

// ---------------- GEMM (R2 layout: thread-per-column, lane-coalesced W) -------
// blockDim.x == C (thread owns one output column); R rows per block.
// Per 4-k chunk: 4 coalesced scalar W loads (1 line/warp-segment each) +
// 16 broadcast float4 X loads (1 line each) for 64 FMAs. FMA-bound.
template<int K, int C>
__device__ __forceinline__ void gemm_body(const float* __restrict__ X,
                                          const float* __restrict__ W,
                                          float* __restrict__ out) {
    constexpr int R = 16;
    const int t    = threadIdx.x;
    const int row0 = blockIdx.x * R;

    float acc[R];
#pragma unroll
    for (int r = 0; r < R; r++) acc[r] = 0.0f;

    for (int k = 0; k < K; k += 4) {
        float w0 = __ldg(&W[(k + 0) * C + t]);
        float w1 = __ldg(&W[(k + 1) * C + t]);
        float w2 = __ldg(&W[(k + 2) * C + t]);
        float w3 = __ldg(&W[(k + 3) * C + t]);
#pragma unroll
        for (int r = 0; r < R; r++) {
            float4 xv = __ldg((const float4*)(X + (size_t)(row0 + r) * K + k));
            acc[r] = fmaf(xv.x, w0, acc[r]);
            acc[r] = fmaf(xv.y, w1, acc[r]);
            acc[r] = fmaf(xv.z, w2, acc[r]);
            acc[r] = fmaf(xv.w, w3, acc[r]);
        }
    }
#pragma unroll
    for (int r = 0; r < R; r++) {
        const int row = row0 + r;   // N_NODES % R == 0
        out[(size_t)row * C + t] = acc[r];
    }
}

__global__ void __launch_bounds__(HID_CH) k_gemm1(const float* __restrict__ X,
                                                  const float* __restrict__ W1) {
    gemm_body<IN_CH, HID_CH>(X, W1, g_h1);
}
__global__ void __launch_bounds__(OUT_CH) k_gemm2(const float* __restrict__ W2) {
    gemm_body<HID_CH, OUT_CH>(g_a1, W2, g_h2);
}

// ---------------- CSR gather aggregation -------------------------------------
// out[v] = (h[v]*dinv[v] + sum_{s in in(v)} h[s]*dinv[s]) * dinv[v] + bias [+relu]
template<int C, bool RELU>
__device__ __forceinline__ void agg_body(const float* __restrict__ h,
                                         const float* __restrict__ bias,
                                         float* __restrict__ out) {
    constexpr int F4 = C / 4;   // float4 lanes per node row
    int gtid = blockIdx.x * blockDim.x + threadIdx.x;
    int node = gtid / F4;
    int j    = gtid % F4;
    if (node >= N_NODES) return;

    const float4* hv = (const float4*)h;
    float dvn = g_dinv[node];

    float4 self = __ldg(&hv[(size_t)node * F4 + j]);
    float4 acc0, acc1;
    acc0.x = self.x * dvn; acc0.y = self.y * dvn;
    acc0.z = self.z * dvn; acc0.w = self.w * dvn;
    acc1 = make_float4(0.f, 0.f, 0.f, 0.f);

    int beg = g_rowptr[node];
    int end = g_rowptr[node + 1];
    int e = beg;
    for (; e + 2 <= end; e += 2) {
        int s0 = g_esrc[e];
        int s1 = g_esrc[e + 1];
        float d0 = g_dinv[s0];
        float d1 = g_dinv[s1];
        float4 v0 = __ldg(&hv[(size_t)s0 * F4 + j]);
        float4 v1 = __ldg(&hv[(size_t)s1 * F4 + j]);
        acc0.x = fmaf(v0.x, d0, acc0.x); acc0.y = fmaf(v0.y, d0, acc0.y);
        acc0.z = fmaf(v0.z, d0, acc0.z); acc0.w = fmaf(v0.w, d0, acc0.w);
        acc1.x = fmaf(v1.x, d1, acc1.x); acc1.y = fmaf(v1.y, d1, acc1.y);
        acc1.z = fmaf(v1.z, d1, acc1.z); acc1.w = fmaf(v1.w, d1, acc1.w);
    }
    if (e < end) {
        int s0 = g_esrc[e];
        float d0 = g_dinv[s0];
        float4 v0 = __ldg(&hv[(size_t)s0 * F4 + j]);
        acc0.x = fmaf(v0.x, d0, acc0.x); acc0.y = fmaf(v0.y, d0, acc0.y);
        acc0.z = fmaf(v0.z, d0, acc0.z); acc0.w = fmaf(v0.w, d0, acc0.w);
    }
    acc0.x += acc1.x; acc0.y += acc1.y; acc0.z += acc1.z; acc0.w += acc1.w;

    float4 b = __ldg(&((const float4*)bias)[j]);
    float4 r;
    r.x = fmaf(acc0.x, dvn, b.x);
    r.y = fmaf(acc0.y, dvn, b.y);
    r.z = fmaf(acc0.z, dvn, b.z);
    r.w = fmaf(acc0.w, dvn, b.w);
    if (RELU) {
        r.x = fmaxf(r.x, 0.0f); r.y = fmaxf(r.y, 0.0f);
        r.z = fmaxf(r.z, 0.0f); r.w = fmaxf(r.w, 0.0f);
    }
    ((float4*)out)[(size_t)node * F4 + j] = r;
}

__global__ void k_agg1(const float* __restrict__ b1) {
    agg_body<HID_CH, true>(g_h1, b1, g_a1);
}
__global__ void k_agg2(const float* __restrict__ b2, float* __restrict__ out) {
    agg_body<OUT_CH, false>(g_h2, b2, out);
}

// ---------------- launch ------------------------------------------------------
extern "C" void kernel_launch(void* const* d_in, const int* in_sizes, int n_in,
                              void* d_out, int out_size) {
    const float* x  = (const float*)d_in[0];
    const void*  ei = d_in[1];
    const float* W1 = (const float*)d_in[2];
    const float* b1 = (const float*)d_in[3];
    const float* W2 = (const float*)d_in[4];
    const float* b2 = (const float*)d_in[5];
    float* out = (float*)d_out;
    (void)in_sizes; (void)n_in; (void)out_size;

    const int TB = 256;

    // #1 prep: dtype detect + counter init
    k_prep     <<<256, TB>>>(ei);
    // #2..#3 CSR degree count + chunk sums
    k_count    <<<(N_EDGES + TB - 1) / TB, TB>>>(ei);
    k_chunksum <<<NCHUNKS, 256>>>();
    // #4 Layer-1 GEMM (independent of CSR; slot #4 = ncu capture target)
    k_gemm1    <<<N_NODES / 16, HID_CH>>>(x, W1);
    // #5..#6 finish CSR: scan + dinv, bucket fill
    k_scanfinal<<<NCHUNKS, CHUNK>>>();
    k_fill     <<<(N_EDGES + TB - 1) / TB, TB>>>(ei);
    // #7 a1 = relu((h1*dinv gathered)*dinv + b1)
    k_agg1     <<<N_NODES * (HID_CH / 4) / TB, TB>>>(b1);
    // #8 Layer-2 GEMM
    k_gemm2    <<<N_NODES / 16, OUT_CH>>>(W2);
    // #9 out = gather(h2)*dinv + b2
    k_agg2     <<<N_NODES * (OUT_CH / 4) / TB, TB>>>(b2, out);
}

// round 6
// speedup vs baseline: 2.4697x; 1.4562x over previous
#include <cuda_runtime.h>
#include <cstdint>

// Problem constants (fixed shapes for GCN_8967891714538)
#define N_NODES 50000
#define N_EDGES 800000
#define IN_CH   128
#define HID_CH  128
#define OUT_CH  64

#define CHUNK   1024
#define NCHUNKS ((N_NODES + CHUNK - 1) / CHUNK)   // 49

// ---------------- scratch (static device globals; no allocation) -------------
__device__ __align__(16) float g_h1 [(size_t)N_NODES * HID_CH];  // x @ W1 (unscaled)
__device__ __align__(16) float g_a1 [(size_t)N_NODES * HID_CH];  // relu(agg1 + b1)
__device__ __align__(16) float g_h2 [(size_t)N_NODES * OUT_CH];  // a1 @ W2 (unscaled)
__device__ float g_dinv[N_NODES];
__device__ int   g_ecnt[N_NODES];
__device__ int   g_fill[N_NODES];
__device__ int   g_rowptr[N_NODES + 1];
__device__ int   g_esrc[N_EDGES];
__device__ int   g_csum[NCHUNKS];
__device__ int   g_is64;   // 1 if edge_index buffer is int64, 0 if int32

// ---------------- edge_index dtype detection ---------------------------------
__device__ __forceinline__ int edge_at(const void* __restrict__ ei, int idx) {
    if (g_is64) return (int)((const long long*)ei)[idx];
    return ((const int*)ei)[idx];
}

// ---------------- prep: detect + init counters --------------------------------
__global__ void k_prep(const void* __restrict__ ei) {
    int gtid = blockIdx.x * blockDim.x + threadIdx.x;
    int nthr = gridDim.x * blockDim.x;

    if (gtid == 0) {
        const long long* p = (const long long*)ei;
        int is64 = 1;
        for (int i = 0; i < 64; i++) {           // 512 bytes — safe for both layouts
            long long v = p[i];
            if (v < 0 || v >= (long long)N_NODES) { is64 = 0; break; }
        }
        g_is64 = is64;
    }
    for (int v = gtid; v < N_NODES; v += nthr) { g_ecnt[v] = 0; g_fill[v] = 0; }
}

// ---------------- CSR build ---------------------------------------------------
__global__ void k_count(const void* __restrict__ ei) {
    int e = blockIdx.x * blockDim.x + threadIdx.x;
    if (e < N_EDGES) {
        int d = edge_at(ei, N_EDGES + e);
        atomicAdd(&g_ecnt[d], 1);
    }
}

__global__ void k_chunksum() {
    __shared__ int sdata[256];
    int c = blockIdx.x, t = threadIdx.x;
    int base = c * CHUNK;
    int s = 0;
    for (int i = t; i < CHUNK; i += 256) {
        int v = base + i;
        s += (v < N_NODES) ? g_ecnt[v] : 0;
    }
    sdata[t] = s;
    __syncthreads();
    for (int off = 128; off > 0; off >>= 1) {
        if (t < off) sdata[t] += sdata[t + off];
        __syncthreads();
    }
    if (t == 0) g_csum[c] = sdata[0];
}

// chunk-local scan + global offset + dinv, all in one kernel (49 blocks x 1024)
__global__ void k_scanfinal() {
    __shared__ int s[CHUNK];
    __shared__ int base;
    int c = blockIdx.x, t = threadIdx.x;
    if (t == 0) {
        int run = 0;
        for (int i = 0; i < c; i++) run += g_csum[i];
        base = run;
    }
    int v = c * CHUNK + t;
    int cnt = (v < N_NODES) ? g_ecnt[v] : 0;
    s[t] = cnt;
    __syncthreads();
    for (int off = 1; off < CHUNK; off <<= 1) {
        int val = (t >= off) ? s[t - off] : 0;
        __syncthreads();
        s[t] += val;
        __syncthreads();
    }
    if (v < N_NODES) {
        g_rowptr[v] = base + s[t] - cnt;           // exclusive
        g_dinv[v]   = rsqrtf((float)(cnt + 1));    // +1 self-loop
    }
    if (c == NCHUNKS - 1 && t == 0) {
        int last = N_NODES - c * CHUNK - 1;
        g_rowptr[N_NODES] = base + s[last];
    }
}

__global__ void k_fill(const void* __restrict__ ei) {
    int e = blockIdx.x * blockDim.x + threadIdx.x;
    if (e < N_EDGES) {
        int sN = edge_at(ei, e);
        int d  = edge_at(ei, N_EDGES + e);
        int pos = g_rowptr[d] + atomicAdd(&g_fill[d], 1);
        g_esrc[pos] = sN;
    }
}

// ---------------- smem-staged GEMM --------------------------------------------
// blockDim = 128. Columns split across tid%C; row-groups across tid/C.
// X tile [R x K] staged ONCE per block via coalesced LDG.128, then read as
// broadcast LDS.128 (conflict-free). W kept in original [K][C] layout so the
// per-k W loads are lane-consecutive (1 line per warp) — the R4 mistake was
// transposing W, NOT the smem staging.
// Per 4-k chunk per thread: 4 coalesced W LDG + RPT broadcast LDS.128 for
// RPT*4 FMAs -> FMA pipe binds.
template<int K, int C, int R>
__device__ __forceinline__ void gemm_body(const float* __restrict__ X,
                                          const float* __restrict__ W,
                                          float* __restrict__ out) {
    constexpr int NT  = 128;
    constexpr int RG  = NT / C;     // row groups per block
    constexpr int RPT = R / RG;     // rows per thread

    __shared__ float sx[R * K];

    const int tid  = threadIdx.x;
    const int row0 = blockIdx.x * R;

    // stage X tile, coalesced float4 loads
#pragma unroll
    for (int j = 0; j < (R * K / 4) / NT; j++) {
        int idx  = j * NT + tid;               // float4 index in tile
        int r    = idx / (K / 4);
        int grow = row0 + r;
        float4 v = make_float4(0.f, 0.f, 0.f, 0.f);
        if (grow < N_NODES)
            v = __ldg((const float4*)(X + (size_t)grow * K) + (idx % (K / 4)));
        ((float4*)sx)[idx] = v;
    }
    __syncthreads();

    const int col   = tid % C;
    const int rbase = (tid / C) * RPT;

    float acc[RPT];
#pragma unroll
    for (int r = 0; r < RPT; r++) acc[r] = 0.0f;

#pragma unroll 4
    for (int kc = 0; kc < K / 4; kc++) {
        const int k = kc * 4;
        float w0 = __ldg(&W[(k + 0) * C + col]);
        float w1 = __ldg(&W[(k + 1) * C + col]);
        float w2 = __ldg(&W[(k + 2) * C + col]);
        float w3 = __ldg(&W[(k + 3) * C + col]);
#pragma unroll
        for (int r = 0; r < RPT; r++) {
            float4 xv = *(const float4*)(sx + (rbase + r) * K + k);
            acc[r] = fmaf(xv.x, w0, acc[r]);
            acc[r] = fmaf(xv.y, w1, acc[r]);
            acc[r] = fmaf(xv.z, w2, acc[r]);
            acc[r] = fmaf(xv.w, w3, acc[r]);
        }
    }

#pragma unroll
    for (int r = 0; r < RPT; r++) {
        int row = row0 + rbase + r;
        if (row < N_NODES)
            out[(size_t)row * C + col] = acc[r];
    }
}

__global__ void __launch_bounds__(128) k_gemm1(const float* __restrict__ X,
                                               const float* __restrict__ W1) {
    gemm_body<IN_CH, HID_CH, 16>(X, W1, g_h1);
}
__global__ void __launch_bounds__(128) k_gemm2(const float* __restrict__ W2) {
    gemm_body<HID_CH, OUT_CH, 32>(g_a1, W2, g_h2);
}

// ---------------- CSR gather aggregation -------------------------------------
// out[v] = (h[v]*dinv[v] + sum_{s in in(v)} h[s]*dinv[s]) * dinv[v] + bias [+relu]
template<int C, bool RELU>
__device__ __forceinline__ void agg_body(const float* __restrict__ h,
                                         const float* __restrict__ bias,
                                         float* __restrict__ out) {
    constexpr int F4 = C / 4;
    int gtid = blockIdx.x * blockDim.x + threadIdx.x;
    int node = gtid / F4;
    int j    = gtid % F4;
    if (node >= N_NODES) return;

    const float4* hv = (const float4*)h;
    float dvn = g_dinv[node];

    float4 self = __ldg(&hv[(size_t)node * F4 + j]);
    float4 acc0, acc1;
    acc0.x = self.x * dvn; acc0.y = self.y * dvn;
    acc0.z = self.z * dvn; acc0.w = self.w * dvn;
    acc1 = make_float4(0.f, 0.f, 0.f, 0.f);

    int beg = g_rowptr[node];
    int end = g_rowptr[node + 1];
    int e = beg;
    for (; e + 2 <= end; e += 2) {
        int s0 = g_esrc[e];
        int s1 = g_esrc[e + 1];
        float d0 = g_dinv[s0];
        float d1 = g_dinv[s1];
        float4 v0 = __ldg(&hv[(size_t)s0 * F4 + j]);
        float4 v1 = __ldg(&hv[(size_t)s1 * F4 + j]);
        acc0.x = fmaf(v0.x, d0, acc0.x); acc0.y = fmaf(v0.y, d0, acc0.y);
        acc0.z = fmaf(v0.z, d0, acc0.z); acc0.w = fmaf(v0.w, d0, acc0.w);
        acc1.x = fmaf(v1.x, d1, acc1.x); acc1.y = fmaf(v1.y, d1, acc1.y);
        acc1.z = fmaf(v1.z, d1, acc1.z); acc1.w = fmaf(v1.w, d1, acc1.w);
    }
    if (e < end) {
        int s0 = g_esrc[e];
        float d0 = g_dinv[s0];
        float4 v0 = __ldg(&hv[(size_t)s0 * F4 + j]);
        acc0.x = fmaf(v0.x, d0, acc0.x); acc0.y = fmaf(v0.y, d0, acc0.y);
        acc0.z = fmaf(v0.z, d0, acc0.z); acc0.w = fmaf(v0.w, d0, acc0.w);
    }
    acc0.x += acc1.x; acc0.y += acc1.y; acc0.z += acc1.z; acc0.w += acc1.w;

    float4 b = __ldg(&((const float4*)bias)[j]);
    float4 r;
    r.x = fmaf(acc0.x, dvn, b.x);
    r.y = fmaf(acc0.y, dvn, b.y);
    r.z = fmaf(acc0.z, dvn, b.z);
    r.w = fmaf(acc0.w, dvn, b.w);
    if (RELU) {
        r.x = fmaxf(r.x, 0.0f); r.y = fmaxf(r.y, 0.0f);
        r.z = fmaxf(r.z, 0.0f); r.w = fmaxf(r.w, 0.0f);
    }
    ((float4*)out)[(size_t)node * F4 + j] = r;
}

__global__ void k_agg1(const float* __restrict__ b1) {
    agg_body<HID_CH, true>(g_h1, b1, g_a1);
}
__global__ void k_agg2(const float* __restrict__ b2, float* __restrict__ out) {
    agg_body<OUT_CH, false>(g_h2, b2, out);
}

// ---------------- launch ------------------------------------------------------
extern "C" void kernel_launch(void* const* d_in, const int* in_sizes, int n_in,
                              void* d_out, int out_size) {
    const float* x  = (const float*)d_in[0];
    const void*  ei = d_in[1];
    const float* W1 = (const float*)d_in[2];
    const float* b1 = (const float*)d_in[3];
    const float* W2 = (const float*)d_in[4];
    const float* b2 = (const float*)d_in[5];
    float* out = (float*)d_out;
    (void)in_sizes; (void)n_in; (void)out_size;

    const int TB = 256;

    // #1 prep: dtype detect + counter init
    k_prep     <<<256, TB>>>(ei);
    // #2..#3 CSR degree count + chunk sums
    k_count    <<<(N_EDGES + TB - 1) / TB, TB>>>(ei);
    k_chunksum <<<NCHUNKS, 256>>>();
    // #4 Layer-1 GEMM (independent of CSR; slot #4 = ncu capture target)
    k_gemm1    <<<(N_NODES + 15) / 16, 128>>>(x, W1);
    // #5..#6 finish CSR: scan + dinv, bucket fill
    k_scanfinal<<<NCHUNKS, CHUNK>>>();
    k_fill     <<<(N_EDGES + TB - 1) / TB, TB>>>(ei);
    // #7 a1 = relu((h1 gathered w/ dinv)*dinv + b1)
    k_agg1     <<<N_NODES * (HID_CH / 4) / TB, TB>>>(b1);
    // #8 Layer-2 GEMM
    k_gemm2    <<<(N_NODES + 31) / 32, 128>>>(W2);
    // #9 out = gather(h2)*dinv + b2
    k_agg2     <<<N_NODES * (OUT_CH / 4) / TB, TB>>>(b2, out);
}

// round 7
// speedup vs baseline: 2.6789x; 1.0847x over previous
#include <cuda_runtime.h>
#include <cstdint>

// Problem constants (fixed shapes for GCN_8967891714538)
#define N_NODES 50000
#define N_EDGES 800000
#define IN_CH   128
#define HID_CH  128
#define OUT_CH  64

#define CHUNK   1024
#define NCHUNKS ((N_NODES + CHUNK - 1) / CHUNK)   // 49

// ---------------- scratch (static device globals; no allocation) -------------
__device__ __align__(16) float g_h1 [(size_t)N_NODES * HID_CH];  // x @ W1 (unscaled)
__device__ __align__(16) float g_a1 [(size_t)N_NODES * HID_CH];  // relu(agg1 + b1)
__device__ __align__(16) float g_h2 [(size_t)N_NODES * OUT_CH];  // a1 @ W2 (unscaled)
__device__ float g_dinv[N_NODES];
__device__ int   g_ecnt[N_NODES];
__device__ int   g_fill[N_NODES];
__device__ int   g_rowptr[N_NODES + 1];
__device__ int   g_esrc[N_EDGES];
__device__ int   g_csum[NCHUNKS];
__device__ int   g_is64;   // 1 if edge_index buffer is int64, 0 if int32

// ---------------- edge_index dtype detection ---------------------------------
__device__ __forceinline__ int edge_at(const void* __restrict__ ei, int idx) {
    if (g_is64) return (int)((const long long*)ei)[idx];
    return ((const int*)ei)[idx];
}

// ---------------- prep: detect + init counters --------------------------------
__global__ void k_prep(const void* __restrict__ ei) {
    int gtid = blockIdx.x * blockDim.x + threadIdx.x;
    int nthr = gridDim.x * blockDim.x;

    if (gtid == 0) {
        const long long* p = (const long long*)ei;
        int is64 = 1;
        for (int i = 0; i < 64; i++) {           // 512 bytes — safe for both layouts
            long long v = p[i];
            if (v < 0 || v >= (long long)N_NODES) { is64 = 0; break; }
        }
        g_is64 = is64;
    }
    for (int v = gtid; v < N_NODES; v += nthr) { g_ecnt[v] = 0; g_fill[v] = 0; }
}

// ---------------- CSR build ---------------------------------------------------
__global__ void k_count(const void* __restrict__ ei) {
    int e = blockIdx.x * blockDim.x + threadIdx.x;
    if (e < N_EDGES) {
        int d = edge_at(ei, N_EDGES + e);
        atomicAdd(&g_ecnt[d], 1);
    }
}

__global__ void k_chunksum() {
    __shared__ int sdata[256];
    int c = blockIdx.x, t = threadIdx.x;
    int base = c * CHUNK;
    int s = 0;
    for (int i = t; i < CHUNK; i += 256) {
        int v = base + i;
        s += (v < N_NODES) ? g_ecnt[v] : 0;
    }
    sdata[t] = s;
    __syncthreads();
    for (int off = 128; off > 0; off >>= 1) {
        if (t < off) sdata[t] += sdata[t + off];
        __syncthreads();
    }
    if (t == 0) g_csum[c] = sdata[0];
}

// chunk-local scan + global offset + dinv, all in one kernel (49 blocks x 1024)
__global__ void k_scanfinal() {
    __shared__ int s[CHUNK];
    __shared__ int base;
    int c = blockIdx.x, t = threadIdx.x;
    if (t == 0) {
        int run = 0;
        for (int i = 0; i < c; i++) run += g_csum[i];
        base = run;
    }
    int v = c * CHUNK + t;
    int cnt = (v < N_NODES) ? g_ecnt[v] : 0;
    s[t] = cnt;
    __syncthreads();
    for (int off = 1; off < CHUNK; off <<= 1) {
        int val = (t >= off) ? s[t - off] : 0;
        __syncthreads();
        s[t] += val;
        __syncthreads();
    }
    if (v < N_NODES) {
        g_rowptr[v] = base + s[t] - cnt;           // exclusive
        g_dinv[v]   = rsqrtf((float)(cnt + 1));    // +1 self-loop
    }
    if (c == NCHUNKS - 1 && t == 0) {
        int last = N_NODES - c * CHUNK - 1;
        g_rowptr[N_NODES] = base + s[last];
    }
}

__global__ void k_fill(const void* __restrict__ ei) {
    int e = blockIdx.x * blockDim.x + threadIdx.x;
    if (e < N_EDGES) {
        int sN = edge_at(ei, e);
        int d  = edge_at(ei, N_EDGES + e);
        int pos = g_rowptr[d] + atomicAdd(&g_fill[d], 1);
        g_esrc[pos] = sN;
    }
}

// ---------------- smem-staged GEMM, 4-col x RPT-row register tile -------------
// blockDim = 128. tx = tid % (C/4) owns cols 4tx..4tx+3; ty = tid / (C/4) owns
// a row group. X tile staged once in smem (coalesced LDG.128), read back as
// broadcast LDS.128. W stays [K][C]: a float4 W load at W[k*C+4tx] spans
// consecutive 16B chunks across lanes -> fully coalesced (R4's bug was the
// TRANSPOSED layout, not smem staging).
// Per 4-k chunk per thread: 4 W LDG.128 + RPT X LDS.128 for RPT*16 FMAs.
template<int K, int C, int R>
__device__ __forceinline__ void gemm_body(const float* __restrict__ X,
                                          const float* __restrict__ W,
                                          float* __restrict__ out) {
    constexpr int NT  = 128;
    constexpr int CT  = C / 4;      // col-threads
    constexpr int RT  = NT / CT;    // row groups per block
    constexpr int RPT = R / RT;     // rows per thread

    __shared__ float sx[R * K];

    const int tid  = threadIdx.x;
    const int row0 = blockIdx.x * R;

    // stage X tile, coalesced float4 loads
#pragma unroll
    for (int j = 0; j < (R * K / 4) / NT; j++) {
        int idx  = j * NT + tid;               // float4 index in tile
        int r    = idx / (K / 4);
        int grow = row0 + r;
        float4 v = make_float4(0.f, 0.f, 0.f, 0.f);
        if (grow < N_NODES)
            v = __ldg((const float4*)(X + (size_t)grow * K) + (idx % (K / 4)));
        ((float4*)sx)[idx] = v;
    }
    __syncthreads();

    const int tx    = tid % CT;
    const int col0  = tx * 4;
    const int rbase = (tid / CT) * RPT;

    float acc[RPT][4];
#pragma unroll
    for (int r = 0; r < RPT; r++)
#pragma unroll
        for (int c = 0; c < 4; c++) acc[r][c] = 0.f;

#pragma unroll 2
    for (int kc = 0; kc < K / 4; kc++) {
        const int k = kc * 4;
        float4 w0 = __ldg((const float4*)(W + (size_t)(k + 0) * C + col0));
        float4 w1 = __ldg((const float4*)(W + (size_t)(k + 1) * C + col0));
        float4 w2 = __ldg((const float4*)(W + (size_t)(k + 2) * C + col0));
        float4 w3 = __ldg((const float4*)(W + (size_t)(k + 3) * C + col0));
#pragma unroll
        for (int r = 0; r < RPT; r++) {
            float4 xv = *(const float4*)(sx + (rbase + r) * K + k);
            acc[r][0] = fmaf(xv.x, w0.x, acc[r][0]);
            acc[r][1] = fmaf(xv.x, w0.y, acc[r][1]);
            acc[r][2] = fmaf(xv.x, w0.z, acc[r][2]);
            acc[r][3] = fmaf(xv.x, w0.w, acc[r][3]);
            acc[r][0] = fmaf(xv.y, w1.x, acc[r][0]);
            acc[r][1] = fmaf(xv.y, w1.y, acc[r][1]);
            acc[r][2] = fmaf(xv.y, w1.z, acc[r][2]);
            acc[r][3] = fmaf(xv.y, w1.w, acc[r][3]);
            acc[r][0] = fmaf(xv.z, w2.x, acc[r][0]);
            acc[r][1] = fmaf(xv.z, w2.y, acc[r][1]);
            acc[r][2] = fmaf(xv.z, w2.z, acc[r][2]);
            acc[r][3] = fmaf(xv.z, w2.w, acc[r][3]);
            acc[r][0] = fmaf(xv.w, w3.x, acc[r][0]);
            acc[r][1] = fmaf(xv.w, w3.y, acc[r][1]);
            acc[r][2] = fmaf(xv.w, w3.z, acc[r][2]);
            acc[r][3] = fmaf(xv.w, w3.w, acc[r][3]);
        }
    }

#pragma unroll
    for (int r = 0; r < RPT; r++) {
        int row = row0 + rbase + r;
        if (row < N_NODES) {
            float4 o = make_float4(acc[r][0], acc[r][1], acc[r][2], acc[r][3]);
            *(float4*)(out + (size_t)row * C + col0) = o;
        }
    }
}

__global__ void __launch_bounds__(128) k_gemm1(const float* __restrict__ X,
                                               const float* __restrict__ W1) {
    gemm_body<IN_CH, HID_CH, 32>(X, W1, g_h1);   // CT=32, RT=4, RPT=8
}
__global__ void __launch_bounds__(128) k_gemm2(const float* __restrict__ W2) {
    gemm_body<HID_CH, OUT_CH, 32>(g_a1, W2, g_h2); // CT=16, RT=8, RPT=4
}

// ---------------- CSR gather aggregation -------------------------------------
// out[v] = (h[v]*dinv[v] + sum_{s in in(v)} h[s]*dinv[s]) * dinv[v] + bias [+relu]
template<int C, bool RELU>
__device__ __forceinline__ void agg_body(const float* __restrict__ h,
                                         const float* __restrict__ bias,
                                         float* __restrict__ out) {
    constexpr int F4 = C / 4;
    int gtid = blockIdx.x * blockDim.x + threadIdx.x;
    int node = gtid / F4;
    int j    = gtid % F4;
    if (node >= N_NODES) return;

    const float4* hv = (const float4*)h;
    float dvn = g_dinv[node];

    float4 self = __ldg(&hv[(size_t)node * F4 + j]);
    float4 acc0, acc1;
    acc0.x = self.x * dvn; acc0.y = self.y * dvn;
    acc0.z = self.z * dvn; acc0.w = self.w * dvn;
    acc1 = make_float4(0.f, 0.f, 0.f, 0.f);

    int beg = g_rowptr[node];
    int end = g_rowptr[node + 1];
    int e = beg;
    for (; e + 2 <= end; e += 2) {
        int s0 = g_esrc[e];
        int s1 = g_esrc[e + 1];
        float d0 = g_dinv[s0];
        float d1 = g_dinv[s1];
        float4 v0 = __ldg(&hv[(size_t)s0 * F4 + j]);
        float4 v1 = __ldg(&hv[(size_t)s1 * F4 + j]);
        acc0.x = fmaf(v0.x, d0, acc0.x); acc0.y = fmaf(v0.y, d0, acc0.y);
        acc0.z = fmaf(v0.z, d0, acc0.z); acc0.w = fmaf(v0.w, d0, acc0.w);
        acc1.x = fmaf(v1.x, d1, acc1.x); acc1.y = fmaf(v1.y, d1, acc1.y);
        acc1.z = fmaf(v1.z, d1, acc1.z); acc1.w = fmaf(v1.w, d1, acc1.w);
    }
    if (e < end) {
        int s0 = g_esrc[e];
        float d0 = g_dinv[s0];
        float4 v0 = __ldg(&hv[(size_t)s0 * F4 + j]);
        acc0.x = fmaf(v0.x, d0, acc0.x); acc0.y = fmaf(v0.y, d0, acc0.y);
        acc0.z = fmaf(v0.z, d0, acc0.z); acc0.w = fmaf(v0.w, d0, acc0.w);
    }
    acc0.x += acc1.x; acc0.y += acc1.y; acc0.z += acc1.z; acc0.w += acc1.w;

    float4 b = __ldg(&((const float4*)bias)[j]);
    float4 r;
    r.x = fmaf(acc0.x, dvn, b.x);
    r.y = fmaf(acc0.y, dvn, b.y);
    r.z = fmaf(acc0.z, dvn, b.z);
    r.w = fmaf(acc0.w, dvn, b.w);
    if (RELU) {
        r.x = fmaxf(r.x, 0.0f); r.y = fmaxf(r.y, 0.0f);
        r.z = fmaxf(r.z, 0.0f); r.w = fmaxf(r.w, 0.0f);
    }
    ((float4*)out)[(size_t)node * F4 + j] = r;
}

__global__ void k_agg1(const float* __restrict__ b1) {
    agg_body<HID_CH, true>(g_h1, b1, g_a1);
}
__global__ void k_agg2(const float* __restrict__ b2, float* __restrict__ out) {
    agg_body<OUT_CH, false>(g_h2, b2, out);
}

// ---------------- launch ------------------------------------------------------
extern "C" void kernel_launch(void* const* d_in, const int* in_sizes, int n_in,
                              void* d_out, int out_size) {
    const float* x  = (const float*)d_in[0];
    const void*  ei = d_in[1];
    const float* W1 = (const float*)d_in[2];
    const float* b1 = (const float*)d_in[3];
    const float* W2 = (const float*)d_in[4];
    const float* b2 = (const float*)d_in[5];
    float* out = (float*)d_out;
    (void)in_sizes; (void)n_in; (void)out_size;

    const int TB = 256;
    const int GR = 32;   // GEMM rows per block

    // #1 prep: dtype detect + counter init
    k_prep     <<<256, TB>>>(ei);
    // #2..#3 CSR degree count + chunk sums
    k_count    <<<(N_EDGES + TB - 1) / TB, TB>>>(ei);
    k_chunksum <<<NCHUNKS, 256>>>();
    // #4 Layer-1 GEMM (independent of CSR; slot #4 = ncu capture target)
    k_gemm1    <<<(N_NODES + GR - 1) / GR, 128>>>(x, W1);
    // #5..#6 finish CSR: scan + dinv, bucket fill
    k_scanfinal<<<NCHUNKS, CHUNK>>>();
    k_fill     <<<(N_EDGES + TB - 1) / TB, TB>>>(ei);
    // #7 a1 = relu((h1 gathered w/ dinv)*dinv + b1)
    k_agg1     <<<N_NODES * (HID_CH / 4) / TB, TB>>>(b1);
    // #8 Layer-2 GEMM
    k_gemm2    <<<(N_NODES + GR - 1) / GR, 128>>>(W2);
    // #9 out = gather(h2)*dinv + b2
    k_agg2     <<<N_NODES * (OUT_CH / 4) / TB, TB>>>(b2, out);
}

// round 8
// speedup vs baseline: 2.8274x; 1.0554x over previous
#include <cuda_runtime.h>
#include <cstdint>

// Problem constants (fixed shapes for GCN_8967891714538)
#define N_NODES 50000
#define N_EDGES 800000
#define IN_CH   128
#define HID_CH  128
#define OUT_CH  64

#define CHUNK   1024
#define NCHUNKS ((N_NODES + CHUNK - 1) / CHUNK)   // 49

// ---------------- scratch (static device globals; no allocation) -------------
__device__ __align__(16) float g_h1 [(size_t)N_NODES * HID_CH];  // x @ W1 (unscaled)
__device__ __align__(16) float g_a1 [(size_t)N_NODES * HID_CH];  // relu(agg1 + b1)
__device__ __align__(16) float g_h2 [(size_t)N_NODES * OUT_CH];  // a1 @ W2 (unscaled)
__device__ float g_dinv[N_NODES];
__device__ int   g_ecnt[N_NODES];
__device__ int   g_fill[N_NODES];
__device__ int   g_rowptr[N_NODES + 1];
__device__ int   g_esrc[N_EDGES];
__device__ int   g_csum[NCHUNKS];
__device__ int   g_is64;   // 1 if edge_index buffer is int64, 0 if int32

// ---------------- edge_index dtype detection ---------------------------------
__device__ __forceinline__ int edge_at(const void* __restrict__ ei, int idx) {
    if (g_is64) return (int)((const long long*)ei)[idx];
    return ((const int*)ei)[idx];
}

// ---------------- prep: detect + init counters --------------------------------
__global__ void k_prep(const void* __restrict__ ei) {
    int gtid = blockIdx.x * blockDim.x + threadIdx.x;
    int nthr = gridDim.x * blockDim.x;

    if (gtid == 0) {
        const long long* p = (const long long*)ei;
        int is64 = 1;
        for (int i = 0; i < 64; i++) {           // 512 bytes — safe for both layouts
            long long v = p[i];
            if (v < 0 || v >= (long long)N_NODES) { is64 = 0; break; }
        }
        g_is64 = is64;
    }
    for (int v = gtid; v < N_NODES; v += nthr) { g_ecnt[v] = 0; g_fill[v] = 0; }
}

// ---------------- CSR build ---------------------------------------------------
__global__ void k_count(const void* __restrict__ ei) {
    int e = blockIdx.x * blockDim.x + threadIdx.x;
    if (e < N_EDGES) {
        int d = edge_at(ei, N_EDGES + e);
        atomicAdd(&g_ecnt[d], 1);
    }
}

__global__ void k_chunksum() {
    __shared__ int sdata[256];
    int c = blockIdx.x, t = threadIdx.x;
    int base = c * CHUNK;
    int s = 0;
    for (int i = t; i < CHUNK; i += 256) {
        int v = base + i;
        s += (v < N_NODES) ? g_ecnt[v] : 0;
    }
    sdata[t] = s;
    __syncthreads();
    for (int off = 128; off > 0; off >>= 1) {
        if (t < off) sdata[t] += sdata[t + off];
        __syncthreads();
    }
    if (t == 0) g_csum[c] = sdata[0];
}

// chunk-local scan + global offset + dinv, all in one kernel (49 blocks x 1024)
__global__ void k_scanfinal() {
    __shared__ int s[CHUNK];
    __shared__ int base;
    int c = blockIdx.x, t = threadIdx.x;
    if (t == 0) {
        int run = 0;
        for (int i = 0; i < c; i++) run += g_csum[i];
        base = run;
    }
    int v = c * CHUNK + t;
    int cnt = (v < N_NODES) ? g_ecnt[v] : 0;
    s[t] = cnt;
    __syncthreads();
    for (int off = 1; off < CHUNK; off <<= 1) {
        int val = (t >= off) ? s[t - off] : 0;
        __syncthreads();
        s[t] += val;
        __syncthreads();
    }
    if (v < N_NODES) {
        g_rowptr[v] = base + s[t] - cnt;           // exclusive
        g_dinv[v]   = rsqrtf((float)(cnt + 1));    // +1 self-loop
    }
    if (c == NCHUNKS - 1 && t == 0) {
        int last = N_NODES - c * CHUNK - 1;
        g_rowptr[N_NODES] = base + s[last];
    }
}

__global__ void k_fill(const void* __restrict__ ei) {
    int e = blockIdx.x * blockDim.x + threadIdx.x;
    if (e < N_EDGES) {
        int sN = edge_at(ei, e);
        int d  = edge_at(ei, N_EDGES + e);
        int pos = g_rowptr[d] + atomicAdd(&g_fill[d], 1);
        g_esrc[pos] = sN;
    }
}

// ---------------- smem-staged GEMM, 4-col x RPT-row register tile -------------
template<int K, int C, int R>
__device__ __forceinline__ void gemm_body(const float* __restrict__ X,
                                          const float* __restrict__ W,
                                          float* __restrict__ out) {
    constexpr int NT  = 128;
    constexpr int CT  = C / 4;      // col-threads
    constexpr int RT  = NT / CT;    // row groups per block
    constexpr int RPT = R / RT;     // rows per thread

    __shared__ float sx[R * K];

    const int tid  = threadIdx.x;
    const int row0 = blockIdx.x * R;

    // stage X tile, coalesced float4 loads
#pragma unroll
    for (int j = 0; j < (R * K / 4) / NT; j++) {
        int idx  = j * NT + tid;               // float4 index in tile
        int r    = idx / (K / 4);
        int grow = row0 + r;
        float4 v = make_float4(0.f, 0.f, 0.f, 0.f);
        if (grow < N_NODES)
            v = __ldg((const float4*)(X + (size_t)grow * K) + (idx % (K / 4)));
        ((float4*)sx)[idx] = v;
    }
    __syncthreads();

    const int tx    = tid % CT;
    const int col0  = tx * 4;
    const int rbase = (tid / CT) * RPT;

    float acc[RPT][4];
#pragma unroll
    for (int r = 0; r < RPT; r++)
#pragma unroll
        for (int c = 0; c < 4; c++) acc[r][c] = 0.f;

#pragma unroll 2
    for (int kc = 0; kc < K / 4; kc++) {
        const int k = kc * 4;
        float4 w0 = __ldg((const float4*)(W + (size_t)(k + 0) * C + col0));
        float4 w1 = __ldg((const float4*)(W + (size_t)(k + 1) * C + col0));
        float4 w2 = __ldg((const float4*)(W + (size_t)(k + 2) * C + col0));
        float4 w3 = __ldg((const float4*)(W + (size_t)(k + 3) * C + col0));
#pragma unroll
        for (int r = 0; r < RPT; r++) {
            float4 xv = *(const float4*)(sx + (rbase + r) * K + k);
            acc[r][0] = fmaf(xv.x, w0.x, acc[r][0]);
            acc[r][1] = fmaf(xv.x, w0.y, acc[r][1]);
            acc[r][2] = fmaf(xv.x, w0.z, acc[r][2]);
            acc[r][3] = fmaf(xv.x, w0.w, acc[r][3]);
            acc[r][0] = fmaf(xv.y, w1.x, acc[r][0]);
            acc[r][1] = fmaf(xv.y, w1.y, acc[r][1]);
            acc[r][2] = fmaf(xv.y, w1.z, acc[r][2]);
            acc[r][3] = fmaf(xv.y, w1.w, acc[r][3]);
            acc[r][0] = fmaf(xv.z, w2.x, acc[r][0]);
            acc[r][1] = fmaf(xv.z, w2.y, acc[r][1]);
            acc[r][2] = fmaf(xv.z, w2.z, acc[r][2]);
            acc[r][3] = fmaf(xv.z, w2.w, acc[r][3]);
            acc[r][0] = fmaf(xv.w, w3.x, acc[r][0]);
            acc[r][1] = fmaf(xv.w, w3.y, acc[r][1]);
            acc[r][2] = fmaf(xv.w, w3.z, acc[r][2]);
            acc[r][3] = fmaf(xv.w, w3.w, acc[r][3]);
        }
    }

#pragma unroll
    for (int r = 0; r < RPT; r++) {
        int row = row0 + rbase + r;
        if (row < N_NODES) {
            float4 o = make_float4(acc[r][0], acc[r][1], acc[r][2], acc[r][3]);
            *(float4*)(out + (size_t)row * C + col0) = o;
        }
    }
}

__global__ void __launch_bounds__(128) k_gemm1(const float* __restrict__ X,
                                               const float* __restrict__ W1) {
    gemm_body<IN_CH, HID_CH, 32>(X, W1, g_h1);   // CT=32, RT=4, RPT=8
}
__global__ void __launch_bounds__(128) k_gemm2(const float* __restrict__ W2) {
    gemm_body<HID_CH, OUT_CH, 32>(g_a1, W2, g_h2); // CT=16, RT=8, RPT=4
}

// ---------------- CSR gather aggregation -------------------------------------
// out[v] = (h[v]*dinv[v] + sum_{s in in(v)} h[s]*dinv[s]) * dinv[v] + bias [+relu]
template<int C, bool RELU>
__device__ __forceinline__ void agg_body(const float* __restrict__ h,
                                         const float* __restrict__ bias,
                                         float* __restrict__ out) {
    constexpr int F4 = C / 4;
    int gtid = blockIdx.x * blockDim.x + threadIdx.x;
    int node = gtid / F4;
    int j    = gtid % F4;
    if (node >= N_NODES) return;

    const float4* hv = (const float4*)h;
    float dvn = g_dinv[node];

    float4 self = __ldg(&hv[(size_t)node * F4 + j]);
    float4 acc0, acc1;
    acc0.x = self.x * dvn; acc0.y = self.y * dvn;
    acc0.z = self.z * dvn; acc0.w = self.w * dvn;
    acc1 = make_float4(0.f, 0.f, 0.f, 0.f);

    int beg = g_rowptr[node];
    int end = g_rowptr[node + 1];
    int e = beg;
    for (; e + 2 <= end; e += 2) {
        int s0 = g_esrc[e];
        int s1 = g_esrc[e + 1];
        float d0 = g_dinv[s0];
        float d1 = g_dinv[s1];
        float4 v0 = __ldg(&hv[(size_t)s0 * F4 + j]);
        float4 v1 = __ldg(&hv[(size_t)s1 * F4 + j]);
        acc0.x = fmaf(v0.x, d0, acc0.x); acc0.y = fmaf(v0.y, d0, acc0.y);
        acc0.z = fmaf(v0.z, d0, acc0.z); acc0.w = fmaf(v0.w, d0, acc0.w);
        acc1.x = fmaf(v1.x, d1, acc1.x); acc1.y = fmaf(v1.y, d1, acc1.y);
        acc1.z = fmaf(v1.z, d1, acc1.z); acc1.w = fmaf(v1.w, d1, acc1.w);
    }
    if (e < end) {
        int s0 = g_esrc[e];
        float d0 = g_dinv[s0];
        float4 v0 = __ldg(&hv[(size_t)s0 * F4 + j]);
        acc0.x = fmaf(v0.x, d0, acc0.x); acc0.y = fmaf(v0.y, d0, acc0.y);
        acc0.z = fmaf(v0.z, d0, acc0.z); acc0.w = fmaf(v0.w, d0, acc0.w);
    }
    acc0.x += acc1.x; acc0.y += acc1.y; acc0.z += acc1.z; acc0.w += acc1.w;

    float4 b = __ldg(&((const float4*)bias)[j]);
    float4 r;
    r.x = fmaf(acc0.x, dvn, b.x);
    r.y = fmaf(acc0.y, dvn, b.y);
    r.z = fmaf(acc0.z, dvn, b.z);
    r.w = fmaf(acc0.w, dvn, b.w);
    if (RELU) {
        r.x = fmaxf(r.x, 0.0f); r.y = fmaxf(r.y, 0.0f);
        r.z = fmaxf(r.z, 0.0f); r.w = fmaxf(r.w, 0.0f);
    }
    ((float4*)out)[(size_t)node * F4 + j] = r;
}

__global__ void k_agg1(const float* __restrict__ b1) {
    agg_body<HID_CH, true>(g_h1, b1, g_a1);
}
__global__ void k_agg2(const float* __restrict__ b2, float* __restrict__ out) {
    agg_body<OUT_CH, false>(g_h2, b2, out);
}

// ---------------- launch ------------------------------------------------------
// Fork-join: gemm1 (fma-bound) runs on the default stream while the whole CSR
// build (atomic/L2-bound) runs on a non-blocking side stream; they join before
// agg1. Graph capture records the event edges as graph dependencies.
// Stream/events are created fresh per call and intentionally leaked:
// kernel_launch itself only runs ~2x (correctness + capture); timed replays
// execute the captured graph. No device memory is allocated.
extern "C" void kernel_launch(void* const* d_in, const int* in_sizes, int n_in,
                              void* d_out, int out_size) {
    const float* x  = (const float*)d_in[0];
    const void*  ei = d_in[1];
    const float* W1 = (const float*)d_in[2];
    const float* b1 = (const float*)d_in[3];
    const float* W2 = (const float*)d_in[4];
    const float* b2 = (const float*)d_in[5];
    float* out = (float*)d_out;
    (void)in_sizes; (void)n_in; (void)out_size;

    const int TB = 256;
    const int GR = 32;   // GEMM rows per block

    cudaStream_t s1;
    cudaStreamCreateWithFlags(&s1, cudaStreamNonBlocking);
    cudaEvent_t evA, evB;
    cudaEventCreateWithFlags(&evA, cudaEventDisableTiming);
    cudaEventCreateWithFlags(&evB, cudaEventDisableTiming);

    // fork: side stream joins the (captured) default stream
    cudaEventRecord(evA, 0);
    cudaStreamWaitEvent(s1, evA, 0);

    // side stream: full CSR build (prep -> count -> chunksum -> scan -> fill)
    k_prep     <<<256, TB, 0, s1>>>(ei);
    k_count    <<<(N_EDGES + TB - 1) / TB, TB, 0, s1>>>(ei);
    k_chunksum <<<NCHUNKS, 256, 0, s1>>>();
    k_scanfinal<<<NCHUNKS, CHUNK, 0, s1>>>();
    k_fill     <<<(N_EDGES + TB - 1) / TB, TB, 0, s1>>>(ei);
    cudaEventRecord(evB, s1);

    // default stream: Layer-1 GEMM overlaps the CSR build
    k_gemm1<<<(N_NODES + GR - 1) / GR, 128>>>(x, W1);

    // join, then the dependent tail
    cudaStreamWaitEvent(0, evB, 0);
    k_agg1 <<<N_NODES * (HID_CH / 4) / TB, TB>>>(b1);
    k_gemm2<<<(N_NODES + GR - 1) / GR, 128>>>(W2);
    k_agg2 <<<N_NODES * (OUT_CH / 4) / TB, TB>>>(b2, out);
}

// round 9
// speedup vs baseline: 2.8324x; 1.0018x over previous
#include <cuda_runtime.h>
#include <cstdint>

// Problem constants (fixed shapes for GCN_8967891714538)
#define N_NODES 50000
#define N_EDGES 800000
#define IN_CH   128
#define HID_CH  128
#define OUT_CH  64

#define CHUNK   1024
#define NCHUNKS ((N_NODES + CHUNK - 1) / CHUNK)   // 49

// ---------------- scratch (static device globals; no allocation) -------------
__device__ __align__(16) float g_h1 [(size_t)N_NODES * HID_CH];  // x @ W1 (unscaled)
__device__ __align__(16) float g_a1 [(size_t)N_NODES * HID_CH];  // relu(agg1 + b1)
__device__ __align__(16) float g_h2 [(size_t)N_NODES * OUT_CH];  // a1 @ W2 (unscaled)
__device__ float g_dinv[N_NODES];
__device__ int   g_ecnt[N_NODES];
__device__ int   g_fill[N_NODES];
__device__ int   g_rowptr[N_NODES + 1];
__device__ int   g_esrc[N_EDGES];
__device__ int   g_csum[NCHUNKS];

// edge_index is int32: JAX reference runs without jax_enable_x64, so the
// "int64" edge_index is silently int32 (confirmed by the R1 OOB crash when
// parsed as 8-byte elements).

// ---------------- prep: init counters ------------------------------------------
__global__ void k_prep() {
    int gtid = blockIdx.x * blockDim.x + threadIdx.x;
    int nthr = gridDim.x * blockDim.x;
    for (int v = gtid; v < N_NODES; v += nthr) { g_ecnt[v] = 0; g_fill[v] = 0; }
}

// ---------------- CSR build ---------------------------------------------------
__global__ void k_count(const int* __restrict__ ei) {
    int e = blockIdx.x * blockDim.x + threadIdx.x;
    if (e < N_EDGES) {
        int d = ei[N_EDGES + e];
        atomicAdd(&g_ecnt[d], 1);
    }
}

__global__ void k_chunksum() {
    __shared__ int sdata[256];
    int c = blockIdx.x, t = threadIdx.x;
    int base = c * CHUNK;
    int s = 0;
    for (int i = t; i < CHUNK; i += 256) {
        int v = base + i;
        s += (v < N_NODES) ? g_ecnt[v] : 0;
    }
    sdata[t] = s;
    __syncthreads();
    for (int off = 128; off > 0; off >>= 1) {
        if (t < off) sdata[t] += sdata[t + off];
        __syncthreads();
    }
    if (t == 0) g_csum[c] = sdata[0];
}

// chunk-local scan + global offset + dinv, all in one kernel (49 blocks x 1024)
__global__ void k_scanfinal() {
    __shared__ int s[CHUNK];
    __shared__ int base;
    int c = blockIdx.x, t = threadIdx.x;
    if (t == 0) {
        int run = 0;
        for (int i = 0; i < c; i++) run += g_csum[i];
        base = run;
    }
    int v = c * CHUNK + t;
    int cnt = (v < N_NODES) ? g_ecnt[v] : 0;
    s[t] = cnt;
    __syncthreads();
    for (int off = 1; off < CHUNK; off <<= 1) {
        int val = (t >= off) ? s[t - off] : 0;
        __syncthreads();
        s[t] += val;
        __syncthreads();
    }
    if (v < N_NODES) {
        g_rowptr[v] = base + s[t] - cnt;           // exclusive
        g_dinv[v]   = rsqrtf((float)(cnt + 1));    // +1 self-loop
    }
    if (c == NCHUNKS - 1 && t == 0) {
        int last = N_NODES - c * CHUNK - 1;
        g_rowptr[N_NODES] = base + s[last];
    }
}

__global__ void k_fill(const int* __restrict__ ei) {
    int e = blockIdx.x * blockDim.x + threadIdx.x;
    if (e < N_EDGES) {
        int sN = ei[e];
        int d  = ei[N_EDGES + e];
        int pos = g_rowptr[d] + atomicAdd(&g_fill[d], 1);
        g_esrc[pos] = sN;
    }
}

// ---------------- smem-staged GEMM, 4-col x RPT-row register tile -------------
template<int K, int C, int R>
__device__ __forceinline__ void gemm_body(const float* __restrict__ X,
                                          const float* __restrict__ W,
                                          float* __restrict__ out) {
    constexpr int NT  = 128;
    constexpr int CT  = C / 4;      // col-threads
    constexpr int RT  = NT / CT;    // row groups per block
    constexpr int RPT = R / RT;     // rows per thread

    __shared__ float sx[R * K];

    const int tid  = threadIdx.x;
    const int row0 = blockIdx.x * R;

    // stage X tile, coalesced float4 loads
#pragma unroll
    for (int j = 0; j < (R * K / 4) / NT; j++) {
        int idx  = j * NT + tid;               // float4 index in tile
        int r    = idx / (K / 4);
        int grow = row0 + r;
        float4 v = make_float4(0.f, 0.f, 0.f, 0.f);
        if (grow < N_NODES)
            v = __ldg((const float4*)(X + (size_t)grow * K) + (idx % (K / 4)));
        ((float4*)sx)[idx] = v;
    }
    __syncthreads();

    const int tx    = tid % CT;
    const int col0  = tx * 4;
    const int rbase = (tid / CT) * RPT;

    float acc[RPT][4];
#pragma unroll
    for (int r = 0; r < RPT; r++)
#pragma unroll
        for (int c = 0; c < 4; c++) acc[r][c] = 0.f;

#pragma unroll 2
    for (int kc = 0; kc < K / 4; kc++) {
        const int k = kc * 4;
        float4 w0 = __ldg((const float4*)(W + (size_t)(k + 0) * C + col0));
        float4 w1 = __ldg((const float4*)(W + (size_t)(k + 1) * C + col0));
        float4 w2 = __ldg((const float4*)(W + (size_t)(k + 2) * C + col0));
        float4 w3 = __ldg((const float4*)(W + (size_t)(k + 3) * C + col0));
#pragma unroll
        for (int r = 0; r < RPT; r++) {
            float4 xv = *(const float4*)(sx + (rbase + r) * K + k);
            acc[r][0] = fmaf(xv.x, w0.x, acc[r][0]);
            acc[r][1] = fmaf(xv.x, w0.y, acc[r][1]);
            acc[r][2] = fmaf(xv.x, w0.z, acc[r][2]);
            acc[r][3] = fmaf(xv.x, w0.w, acc[r][3]);
            acc[r][0] = fmaf(xv.y, w1.x, acc[r][0]);
            acc[r][1] = fmaf(xv.y, w1.y, acc[r][1]);
            acc[r][2] = fmaf(xv.y, w1.z, acc[r][2]);
            acc[r][3] = fmaf(xv.y, w1.w, acc[r][3]);
            acc[r][0] = fmaf(xv.z, w2.x, acc[r][0]);
            acc[r][1] = fmaf(xv.z, w2.y, acc[r][1]);
            acc[r][2] = fmaf(xv.z, w2.z, acc[r][2]);
            acc[r][3] = fmaf(xv.z, w2.w, acc[r][3]);
            acc[r][0] = fmaf(xv.w, w3.x, acc[r][0]);
            acc[r][1] = fmaf(xv.w, w3.y, acc[r][1]);
            acc[r][2] = fmaf(xv.w, w3.z, acc[r][2]);
            acc[r][3] = fmaf(xv.w, w3.w, acc[r][3]);
        }
    }

#pragma unroll
    for (int r = 0; r < RPT; r++) {
        int row = row0 + rbase + r;
        if (row < N_NODES) {
            float4 o = make_float4(acc[r][0], acc[r][1], acc[r][2], acc[r][3]);
            *(float4*)(out + (size_t)row * C + col0) = o;
        }
    }
}

__global__ void __launch_bounds__(128) k_gemm1(const float* __restrict__ X,
                                               const float* __restrict__ W1) {
    gemm_body<IN_CH, HID_CH, 32>(X, W1, g_h1);   // CT=32, RT=4, RPT=8
}
__global__ void __launch_bounds__(128) k_gemm2(const float* __restrict__ W2) {
    gemm_body<HID_CH, OUT_CH, 32>(g_a1, W2, g_h2); // CT=16, RT=8, RPT=4
}

// ---------------- CSR gather aggregation -------------------------------------
// out[v] = (h[v]*dinv[v] + sum_{s in in(v)} h[s]*dinv[s]) * dinv[v] + bias [+relu]
// Unroll 4 with independent accumulators (MLP=4); row/dinv gathers bypass L1
// (__ldcg) since the 25.6MB table cannot live in 228KB L1.
template<int C, bool RELU>
__device__ __forceinline__ void agg_body(const float* __restrict__ h,
                                         const float* __restrict__ bias,
                                         float* __restrict__ out) {
    constexpr int F4 = C / 4;
    int gtid = blockIdx.x * blockDim.x + threadIdx.x;
    int node = gtid / F4;
    int j    = gtid % F4;
    if (node >= N_NODES) return;

    const float4* hv = (const float4*)h;
    float dvn = g_dinv[node];

    float4 self = __ldcg(&hv[(size_t)node * F4 + j]);
    float4 a0, a1, a2, a3;
    a0.x = self.x * dvn; a0.y = self.y * dvn;
    a0.z = self.z * dvn; a0.w = self.w * dvn;
    a1 = make_float4(0.f, 0.f, 0.f, 0.f);
    a2 = make_float4(0.f, 0.f, 0.f, 0.f);
    a3 = make_float4(0.f, 0.f, 0.f, 0.f);

    const int beg = g_rowptr[node];
    const int end = g_rowptr[node + 1];
    int e = beg;
    for (; e + 4 <= end; e += 4) {
        int s0 = __ldg(&g_esrc[e + 0]);
        int s1 = __ldg(&g_esrc[e + 1]);
        int s2 = __ldg(&g_esrc[e + 2]);
        int s3 = __ldg(&g_esrc[e + 3]);
        float d0 = __ldcg(&g_dinv[s0]);
        float d1 = __ldcg(&g_dinv[s1]);
        float d2 = __ldcg(&g_dinv[s2]);
        float d3 = __ldcg(&g_dinv[s3]);
        float4 v0 = __ldcg(&hv[(size_t)s0 * F4 + j]);
        float4 v1 = __ldcg(&hv[(size_t)s1 * F4 + j]);
        float4 v2 = __ldcg(&hv[(size_t)s2 * F4 + j]);
        float4 v3 = __ldcg(&hv[(size_t)s3 * F4 + j]);
        a0.x = fmaf(v0.x, d0, a0.x); a0.y = fmaf(v0.y, d0, a0.y);
        a0.z = fmaf(v0.z, d0, a0.z); a0.w = fmaf(v0.w, d0, a0.w);
        a1.x = fmaf(v1.x, d1, a1.x); a1.y = fmaf(v1.y, d1, a1.y);
        a1.z = fmaf(v1.z, d1, a1.z); a1.w = fmaf(v1.w, d1, a1.w);
        a2.x = fmaf(v2.x, d2, a2.x); a2.y = fmaf(v2.y, d2, a2.y);
        a2.z = fmaf(v2.z, d2, a2.z); a2.w = fmaf(v2.w, d2, a2.w);
        a3.x = fmaf(v3.x, d3, a3.x); a3.y = fmaf(v3.y, d3, a3.y);
        a3.z = fmaf(v3.z, d3, a3.z); a3.w = fmaf(v3.w, d3, a3.w);
    }
    for (; e < end; e++) {
        int s0 = __ldg(&g_esrc[e]);
        float d0 = __ldcg(&g_dinv[s0]);
        float4 v0 = __ldcg(&hv[(size_t)s0 * F4 + j]);
        a0.x = fmaf(v0.x, d0, a0.x); a0.y = fmaf(v0.y, d0, a0.y);
        a0.z = fmaf(v0.z, d0, a0.z); a0.w = fmaf(v0.w, d0, a0.w);
    }
    a0.x += a1.x + a2.x + a3.x;
    a0.y += a1.y + a2.y + a3.y;
    a0.z += a1.z + a2.z + a3.z;
    a0.w += a1.w + a2.w + a3.w;

    float4 b = __ldg(&((const float4*)bias)[j]);
    float4 r;
    r.x = fmaf(a0.x, dvn, b.x);
    r.y = fmaf(a0.y, dvn, b.y);
    r.z = fmaf(a0.z, dvn, b.z);
    r.w = fmaf(a0.w, dvn, b.w);
    if (RELU) {
        r.x = fmaxf(r.x, 0.0f); r.y = fmaxf(r.y, 0.0f);
        r.z = fmaxf(r.z, 0.0f); r.w = fmaxf(r.w, 0.0f);
    }
    ((float4*)out)[(size_t)node * F4 + j] = r;
}

__global__ void k_agg1(const float* __restrict__ b1) {
    agg_body<HID_CH, true>(g_h1, b1, g_a1);
}
__global__ void k_agg2(const float* __restrict__ b2, float* __restrict__ out) {
    agg_body<OUT_CH, false>(g_h2, b2, out);
}

// ---------------- launch ------------------------------------------------------
// Fork-join: gemm1 (fma-bound) on the default stream overlaps the CSR build
// (atomic/L2-bound) on a side stream; join before agg1. Stream/events created
// per call and leaked (kernel_launch runs ~2x; replays execute the graph).
extern "C" void kernel_launch(void* const* d_in, const int* in_sizes, int n_in,
                              void* d_out, int out_size) {
    const float* x  = (const float*)d_in[0];
    const int*   ei = (const int*)d_in[1];
    const float* W1 = (const float*)d_in[2];
    const float* b1 = (const float*)d_in[3];
    const float* W2 = (const float*)d_in[4];
    const float* b2 = (const float*)d_in[5];
    float* out = (float*)d_out;
    (void)in_sizes; (void)n_in; (void)out_size;

    const int TB = 256;
    const int GR = 32;   // GEMM rows per block

    cudaStream_t s1;
    cudaStreamCreateWithFlags(&s1, cudaStreamNonBlocking);
    cudaEvent_t evA, evB;
    cudaEventCreateWithFlags(&evA, cudaEventDisableTiming);
    cudaEventCreateWithFlags(&evB, cudaEventDisableTiming);

    // fork: side stream joins the (captured) default stream
    cudaEventRecord(evA, 0);
    cudaStreamWaitEvent(s1, evA, 0);

    // side stream: full CSR build (prep -> count -> chunksum -> scan -> fill)
    k_prep     <<<256, TB, 0, s1>>>();
    k_count    <<<(N_EDGES + TB - 1) / TB, TB, 0, s1>>>(ei);
    k_chunksum <<<NCHUNKS, 256, 0, s1>>>();
    k_scanfinal<<<NCHUNKS, CHUNK, 0, s1>>>();
    k_fill     <<<(N_EDGES + TB - 1) / TB, TB, 0, s1>>>(ei);
    cudaEventRecord(evB, s1);

    // default stream: Layer-1 GEMM overlaps the CSR build
    k_gemm1<<<(N_NODES + GR - 1) / GR, 128>>>(x, W1);

    // join, then the dependent tail
    cudaStreamWaitEvent(0, evB, 0);
    k_agg1 <<<N_NODES * (HID_CH / 4) / TB, TB>>>(b1);
    k_gemm2<<<(N_NODES + GR - 1) / GR, 128>>>(W2);
    k_agg2 <<<N_NODES * (OUT_CH / 4) / TB, TB>>>(b2, out);
}

// round 10
// speedup vs baseline: 3.1070x; 1.0969x over previous
#include <cuda_runtime.h>
#include <cstdint>

// Problem constants (fixed shapes for GCN_8967891714538)
#define N_NODES 50000
#define N_EDGES 800000
#define IN_CH   128
#define HID_CH  128
#define OUT_CH  64

#define CHUNK   1024
#define NCHUNKS ((N_NODES + CHUNK - 1) / CHUNK)   // 49

// ---------------- scratch (static device globals; no allocation) -------------
__device__ __align__(16) float g_h1 [(size_t)N_NODES * HID_CH];  // x @ W1 (unscaled)
__device__ __align__(16) float g_h2 [(size_t)N_NODES * OUT_CH];  // a1 @ W2 (unscaled)
__device__ float g_dinv[N_NODES];
__device__ int   g_ecnt[N_NODES];
__device__ int   g_fill[N_NODES];
__device__ int   g_rowptr[N_NODES + 1];
__device__ int   g_esrc[N_EDGES];
__device__ int   g_csum[NCHUNKS];

// edge_index is int32 (JAX default x64-disabled; R1 OOB crash confirmed 4-byte).

// ---------------- prep: init counters ------------------------------------------
__global__ void k_prep() {
    int gtid = blockIdx.x * blockDim.x + threadIdx.x;
    int nthr = gridDim.x * blockDim.x;
    for (int v = gtid; v < N_NODES; v += nthr) { g_ecnt[v] = 0; g_fill[v] = 0; }
}

// ---------------- CSR build ---------------------------------------------------
__global__ void k_count(const int* __restrict__ ei) {
    int e = blockIdx.x * blockDim.x + threadIdx.x;
    if (e < N_EDGES) {
        int d = ei[N_EDGES + e];
        atomicAdd(&g_ecnt[d], 1);
    }
}

__global__ void k_chunksum() {
    __shared__ int sdata[256];
    int c = blockIdx.x, t = threadIdx.x;
    int base = c * CHUNK;
    int s = 0;
    for (int i = t; i < CHUNK; i += 256) {
        int v = base + i;
        s += (v < N_NODES) ? g_ecnt[v] : 0;
    }
    sdata[t] = s;
    __syncthreads();
    for (int off = 128; off > 0; off >>= 1) {
        if (t < off) sdata[t] += sdata[t + off];
        __syncthreads();
    }
    if (t == 0) g_csum[c] = sdata[0];
}

// chunk-local scan + global offset + dinv, all in one kernel (49 blocks x 1024)
__global__ void k_scanfinal() {
    __shared__ int s[CHUNK];
    __shared__ int base;
    int c = blockIdx.x, t = threadIdx.x;
    if (t == 0) {
        int run = 0;
        for (int i = 0; i < c; i++) run += g_csum[i];
        base = run;
    }
    int v = c * CHUNK + t;
    int cnt = (v < N_NODES) ? g_ecnt[v] : 0;
    s[t] = cnt;
    __syncthreads();
    for (int off = 1; off < CHUNK; off <<= 1) {
        int val = (t >= off) ? s[t - off] : 0;
        __syncthreads();
        s[t] += val;
        __syncthreads();
    }
    if (v < N_NODES) {
        g_rowptr[v] = base + s[t] - cnt;           // exclusive
        g_dinv[v]   = rsqrtf((float)(cnt + 1));    // +1 self-loop
    }
    if (c == NCHUNKS - 1 && t == 0) {
        int last = N_NODES - c * CHUNK - 1;
        g_rowptr[N_NODES] = base + s[last];
    }
}

__global__ void k_fill(const int* __restrict__ ei) {
    int e = blockIdx.x * blockDim.x + threadIdx.x;
    if (e < N_EDGES) {
        int sN = ei[e];
        int d  = ei[N_EDGES + e];
        int pos = g_rowptr[d] + atomicAdd(&g_fill[d], 1);
        g_esrc[pos] = sN;
    }
}

// ---------------- smem-staged GEMM (layer 1) -----------------------------------
template<int K, int C, int R>
__device__ __forceinline__ void gemm_body(const float* __restrict__ X,
                                          const float* __restrict__ W,
                                          float* __restrict__ out) {
    constexpr int NT  = 128;
    constexpr int CT  = C / 4;      // col-threads
    constexpr int RT  = NT / CT;    // row groups per block
    constexpr int RPT = R / RT;     // rows per thread

    __shared__ float sx[R * K];

    const int tid  = threadIdx.x;
    const int row0 = blockIdx.x * R;

#pragma unroll
    for (int j = 0; j < (R * K / 4) / NT; j++) {
        int idx  = j * NT + tid;
        int r    = idx / (K / 4);
        int grow = row0 + r;
        float4 v = make_float4(0.f, 0.f, 0.f, 0.f);
        if (grow < N_NODES)
            v = __ldg((const float4*)(X + (size_t)grow * K) + (idx % (K / 4)));
        ((float4*)sx)[idx] = v;
    }
    __syncthreads();

    const int tx    = tid % CT;
    const int col0  = tx * 4;
    const int rbase = (tid / CT) * RPT;

    float acc[RPT][4];
#pragma unroll
    for (int r = 0; r < RPT; r++)
#pragma unroll
        for (int c = 0; c < 4; c++) acc[r][c] = 0.f;

#pragma unroll 2
    for (int kc = 0; kc < K / 4; kc++) {
        const int k = kc * 4;
        float4 w0 = __ldg((const float4*)(W + (size_t)(k + 0) * C + col0));
        float4 w1 = __ldg((const float4*)(W + (size_t)(k + 1) * C + col0));
        float4 w2 = __ldg((const float4*)(W + (size_t)(k + 2) * C + col0));
        float4 w3 = __ldg((const float4*)(W + (size_t)(k + 3) * C + col0));
#pragma unroll
        for (int r = 0; r < RPT; r++) {
            float4 xv = *(const float4*)(sx + (rbase + r) * K + k);
            acc[r][0] = fmaf(xv.x, w0.x, acc[r][0]);
            acc[r][1] = fmaf(xv.x, w0.y, acc[r][1]);
            acc[r][2] = fmaf(xv.x, w0.z, acc[r][2]);
            acc[r][3] = fmaf(xv.x, w0.w, acc[r][3]);
            acc[r][0] = fmaf(xv.y, w1.x, acc[r][0]);
            acc[r][1] = fmaf(xv.y, w1.y, acc[r][1]);
            acc[r][2] = fmaf(xv.y, w1.z, acc[r][2]);
            acc[r][3] = fmaf(xv.y, w1.w, acc[r][3]);
            acc[r][0] = fmaf(xv.z, w2.x, acc[r][0]);
            acc[r][1] = fmaf(xv.z, w2.y, acc[r][1]);
            acc[r][2] = fmaf(xv.z, w2.z, acc[r][2]);
            acc[r][3] = fmaf(xv.z, w2.w, acc[r][3]);
            acc[r][0] = fmaf(xv.w, w3.x, acc[r][0]);
            acc[r][1] = fmaf(xv.w, w3.y, acc[r][1]);
            acc[r][2] = fmaf(xv.w, w3.z, acc[r][2]);
            acc[r][3] = fmaf(xv.w, w3.w, acc[r][3]);
        }
    }

#pragma unroll
    for (int r = 0; r < RPT; r++) {
        int row = row0 + rbase + r;
        if (row < N_NODES) {
            float4 o = make_float4(acc[r][0], acc[r][1], acc[r][2], acc[r][3]);
            *(float4*)(out + (size_t)row * C + col0) = o;
        }
    }
}

__global__ void __launch_bounds__(128) k_gemm1(const float* __restrict__ X,
                                               const float* __restrict__ W1) {
    gemm_body<IN_CH, HID_CH, 32>(X, W1, g_h1);   // CT=32, RT=4, RPT=8
}

// ---------------- fused agg1 + gemm2 -------------------------------------------
// Phase 1: 8 warps x 4 nodes each aggregate a1 rows (gather from g_h1, scale,
//          bias, relu) straight into a 32x128 smem tile — a1 never hits global.
// Phase 2: same 256 threads run the gemm2 register tile on the smem tile,
//          writing h2 = a1 @ W2. Overlaps FMA work with gather latency and
//          saves ~51MB of L2 traffic (a1 write+read) vs separate kernels.
__global__ void __launch_bounds__(256) k_agg1gemm2(const float* __restrict__ b1,
                                                   const float* __restrict__ W2) {
    constexpr int RN = 32;                  // nodes per block
    __shared__ float sa[RN * HID_CH];       // 16 KB a1 tile

    const int tid  = threadIdx.x;
    const int w    = tid >> 5;              // warp 0..7
    const int lane = tid & 31;              // j index (F4 = 32)
    const int nbase = blockIdx.x * RN;

    const float4* hv = (const float4*)g_h1;
    float4 b = __ldg(&((const float4*)b1)[lane]);

    // ---- phase 1: aggregate 4 nodes per warp ----
#pragma unroll
    for (int i = 0; i < 4; i++) {
        int node = nbase + w * 4 + i;
        float4 r = make_float4(0.f, 0.f, 0.f, 0.f);
        if (node < N_NODES) {
            float dvn = g_dinv[node];
            float4 self = __ldcg(&hv[(size_t)node * 32 + lane]);
            float4 a0, a1v;
            a0.x = self.x * dvn; a0.y = self.y * dvn;
            a0.z = self.z * dvn; a0.w = self.w * dvn;
            a1v = make_float4(0.f, 0.f, 0.f, 0.f);

            const int beg = g_rowptr[node];
            const int end = g_rowptr[node + 1];
            int e = beg;
            for (; e + 2 <= end; e += 2) {
                int s0 = __ldg(&g_esrc[e + 0]);
                int s1 = __ldg(&g_esrc[e + 1]);
                float d0 = __ldcg(&g_dinv[s0]);
                float d1 = __ldcg(&g_dinv[s1]);
                float4 v0 = __ldcg(&hv[(size_t)s0 * 32 + lane]);
                float4 v1 = __ldcg(&hv[(size_t)s1 * 32 + lane]);
                a0.x = fmaf(v0.x, d0, a0.x); a0.y = fmaf(v0.y, d0, a0.y);
                a0.z = fmaf(v0.z, d0, a0.z); a0.w = fmaf(v0.w, d0, a0.w);
                a1v.x = fmaf(v1.x, d1, a1v.x); a1v.y = fmaf(v1.y, d1, a1v.y);
                a1v.z = fmaf(v1.z, d1, a1v.z); a1v.w = fmaf(v1.w, d1, a1v.w);
            }
            if (e < end) {
                int s0 = __ldg(&g_esrc[e]);
                float d0 = __ldcg(&g_dinv[s0]);
                float4 v0 = __ldcg(&hv[(size_t)s0 * 32 + lane]);
                a0.x = fmaf(v0.x, d0, a0.x); a0.y = fmaf(v0.y, d0, a0.y);
                a0.z = fmaf(v0.z, d0, a0.z); a0.w = fmaf(v0.w, d0, a0.w);
            }
            a0.x += a1v.x; a0.y += a1v.y; a0.z += a1v.z; a0.w += a1v.w;

            r.x = fmaxf(fmaf(a0.x, dvn, b.x), 0.f);
            r.y = fmaxf(fmaf(a0.y, dvn, b.y), 0.f);
            r.z = fmaxf(fmaf(a0.z, dvn, b.z), 0.f);
            r.w = fmaxf(fmaf(a0.w, dvn, b.w), 0.f);
        }
        *(float4*)(sa + (w * 4 + i) * HID_CH + lane * 4) = r;
    }
    __syncthreads();

    // ---- phase 2: h2[32 x 64] = sa[32 x 128] @ W2[128 x 64] ----
    constexpr int C   = OUT_CH;     // 64
    constexpr int CT  = C / 4;      // 16 col-threads
    constexpr int RPT = 2;          // 256 threads / 16 = 16 row groups * 2 rows
    const int tx    = tid % CT;
    const int col0  = tx * 4;
    const int rbase = (tid / CT) * RPT;

    float acc[RPT][4];
#pragma unroll
    for (int r = 0; r < RPT; r++)
#pragma unroll
        for (int c = 0; c < 4; c++) acc[r][c] = 0.f;

#pragma unroll 2
    for (int kc = 0; kc < HID_CH / 4; kc++) {
        const int k = kc * 4;
        float4 w0 = __ldg((const float4*)(W2 + (size_t)(k + 0) * C + col0));
        float4 w1 = __ldg((const float4*)(W2 + (size_t)(k + 1) * C + col0));
        float4 w2 = __ldg((const float4*)(W2 + (size_t)(k + 2) * C + col0));
        float4 w3 = __ldg((const float4*)(W2 + (size_t)(k + 3) * C + col0));
#pragma unroll
        for (int r = 0; r < RPT; r++) {
            float4 xv = *(const float4*)(sa + (rbase + r) * HID_CH + k);
            acc[r][0] = fmaf(xv.x, w0.x, acc[r][0]);
            acc[r][1] = fmaf(xv.x, w0.y, acc[r][1]);
            acc[r][2] = fmaf(xv.x, w0.z, acc[r][2]);
            acc[r][3] = fmaf(xv.x, w0.w, acc[r][3]);
            acc[r][0] = fmaf(xv.y, w1.x, acc[r][0]);
            acc[r][1] = fmaf(xv.y, w1.y, acc[r][1]);
            acc[r][2] = fmaf(xv.y, w1.z, acc[r][2]);
            acc[r][3] = fmaf(xv.y, w1.w, acc[r][3]);
            acc[r][0] = fmaf(xv.z, w2.x, acc[r][0]);
            acc[r][1] = fmaf(xv.z, w2.y, acc[r][1]);
            acc[r][2] = fmaf(xv.z, w2.z, acc[r][2]);
            acc[r][3] = fmaf(xv.z, w2.w, acc[r][3]);
            acc[r][0] = fmaf(xv.w, w3.x, acc[r][0]);
            acc[r][1] = fmaf(xv.w, w3.y, acc[r][1]);
            acc[r][2] = fmaf(xv.w, w3.z, acc[r][2]);
            acc[r][3] = fmaf(xv.w, w3.w, acc[r][3]);
        }
    }

#pragma unroll
    for (int r = 0; r < RPT; r++) {
        int row = nbase + rbase + r;
        if (row < N_NODES) {
            float4 o = make_float4(acc[r][0], acc[r][1], acc[r][2], acc[r][3]);
            *(float4*)(g_h2 + (size_t)row * C + col0) = o;
        }
    }
}

// ---------------- layer-2 aggregation ------------------------------------------
// out[v] = (h2[v]*dinv[v] + sum_s h2[s]*dinv[s]) * dinv[v] + b2
__global__ void k_agg2(const float* __restrict__ b2, float* __restrict__ out) {
    constexpr int F4 = OUT_CH / 4;   // 16
    int gtid = blockIdx.x * blockDim.x + threadIdx.x;
    int node = gtid / F4;
    int j    = gtid % F4;
    if (node >= N_NODES) return;

    const float4* hv = (const float4*)g_h2;
    float dvn = g_dinv[node];

    float4 self = __ldcg(&hv[(size_t)node * F4 + j]);
    float4 a0, a1;
    a0.x = self.x * dvn; a0.y = self.y * dvn;
    a0.z = self.z * dvn; a0.w = self.w * dvn;
    a1 = make_float4(0.f, 0.f, 0.f, 0.f);

    const int beg = g_rowptr[node];
    const int end = g_rowptr[node + 1];
    int e = beg;
    for (; e + 2 <= end; e += 2) {
        int s0 = __ldg(&g_esrc[e + 0]);
        int s1 = __ldg(&g_esrc[e + 1]);
        float d0 = __ldcg(&g_dinv[s0]);
        float d1 = __ldcg(&g_dinv[s1]);
        float4 v0 = __ldcg(&hv[(size_t)s0 * F4 + j]);
        float4 v1 = __ldcg(&hv[(size_t)s1 * F4 + j]);
        a0.x = fmaf(v0.x, d0, a0.x); a0.y = fmaf(v0.y, d0, a0.y);
        a0.z = fmaf(v0.z, d0, a0.z); a0.w = fmaf(v0.w, d0, a0.w);
        a1.x = fmaf(v1.x, d1, a1.x); a1.y = fmaf(v1.y, d1, a1.y);
        a1.z = fmaf(v1.z, d1, a1.z); a1.w = fmaf(v1.w, d1, a1.w);
    }
    if (e < end) {
        int s0 = __ldg(&g_esrc[e]);
        float d0 = __ldcg(&g_dinv[s0]);
        float4 v0 = __ldcg(&hv[(size_t)s0 * F4 + j]);
        a0.x = fmaf(v0.x, d0, a0.x); a0.y = fmaf(v0.y, d0, a0.y);
        a0.z = fmaf(v0.z, d0, a0.z); a0.w = fmaf(v0.w, d0, a0.w);
    }
    a0.x += a1.x; a0.y += a1.y; a0.z += a1.z; a0.w += a1.w;

    float4 b = __ldg(&((const float4*)b2)[j]);
    float4 r;
    r.x = fmaf(a0.x, dvn, b.x);
    r.y = fmaf(a0.y, dvn, b.y);
    r.z = fmaf(a0.z, dvn, b.z);
    r.w = fmaf(a0.w, dvn, b.w);
    ((float4*)out)[(size_t)node * F4 + j] = r;
}

// ---------------- launch ------------------------------------------------------
// Fork-join: gemm1 (fma-bound) on the default stream overlaps the CSR build
// (atomic/L2-bound) on a side stream; join before the fused agg1+gemm2.
// Stream/events created per call and leaked (kernel_launch runs ~2x; timed
// replays execute the captured graph). No device memory allocated.
extern "C" void kernel_launch(void* const* d_in, const int* in_sizes, int n_in,
                              void* d_out, int out_size) {
    const float* x  = (const float*)d_in[0];
    const int*   ei = (const int*)d_in[1];
    const float* W1 = (const float*)d_in[2];
    const float* b1 = (const float*)d_in[3];
    const float* W2 = (const float*)d_in[4];
    const float* b2 = (const float*)d_in[5];
    float* out = (float*)d_out;
    (void)in_sizes; (void)n_in; (void)out_size;

    const int TB = 256;
    const int GR = 32;   // rows per block (gemm1 tile / fused tile)

    cudaStream_t s1;
    cudaStreamCreateWithFlags(&s1, cudaStreamNonBlocking);
    cudaEvent_t evA, evB;
    cudaEventCreateWithFlags(&evA, cudaEventDisableTiming);
    cudaEventCreateWithFlags(&evB, cudaEventDisableTiming);

    // fork: side stream joins the (captured) default stream
    cudaEventRecord(evA, 0);
    cudaStreamWaitEvent(s1, evA, 0);

    // side stream: full CSR build (prep -> count -> chunksum -> scan -> fill)
    k_prep     <<<256, TB, 0, s1>>>();
    k_count    <<<(N_EDGES + TB - 1) / TB, TB, 0, s1>>>(ei);
    k_chunksum <<<NCHUNKS, 256, 0, s1>>>();
    k_scanfinal<<<NCHUNKS, CHUNK, 0, s1>>>();
    k_fill     <<<(N_EDGES + TB - 1) / TB, TB, 0, s1>>>(ei);
    cudaEventRecord(evB, s1);

    // default stream: Layer-1 GEMM overlaps the CSR build
    k_gemm1<<<(N_NODES + GR - 1) / GR, 128>>>(x, W1);

    // join, then fused agg1+gemm2 and final aggregation
    cudaStreamWaitEvent(0, evB, 0);
    k_agg1gemm2<<<(N_NODES + GR - 1) / GR, 256>>>(b1, W2);
    k_agg2     <<<N_NODES * (OUT_CH / 4) / TB, TB>>>(b2, out);
}

// round 11
// speedup vs baseline: 3.3977x; 1.0936x over previous
#include <cuda_runtime.h>
#include <cuda_fp16.h>
#include <cstdint>

// Problem constants (fixed shapes for GCN_8967891714538)
#define N_NODES 50000
#define N_EDGES 800000
#define IN_CH   128
#define HID_CH  128
#define OUT_CH  64

#define CHUNK   1024
#define NCHUNKS ((N_NODES + CHUNK - 1) / CHUNK)   // 49

// ---------------- scratch (static device globals; no allocation) -------------
// h1/h2 stored fp16 (accumulation stays fp32): halves the agg gather traffic,
// which sits at the LTS-throughput floor (R9 showed ILP doesn't move it).
__device__ __align__(16) __half g_h1[(size_t)N_NODES * HID_CH];  // x @ W1
__device__ __align__(16) __half g_h2[(size_t)N_NODES * OUT_CH];  // a1 @ W2
__device__ float g_dinv[N_NODES];
__device__ int   g_ecnt[N_NODES];
__device__ int   g_fill[N_NODES];
__device__ int   g_rowptr[N_NODES + 1];
__device__ int   g_esrc[N_EDGES];
__device__ int   g_csum[NCHUNKS];

// edge_index is int32 (JAX default x64-disabled; R1 OOB crash confirmed 4-byte).

__device__ __forceinline__ float4 half4_to_float4(uint2 u) {
    __half2 h0 = *(__half2*)&u.x;
    __half2 h1 = *(__half2*)&u.y;
    float2 f0 = __half22float2(h0);
    float2 f1 = __half22float2(h1);
    return make_float4(f0.x, f0.y, f1.x, f1.y);
}
__device__ __forceinline__ uint2 float4_to_half4(float a, float b, float c, float d) {
    __half2 h0 = __floats2half2_rn(a, b);
    __half2 h1 = __floats2half2_rn(c, d);
    uint2 u;
    u.x = *(unsigned*)&h0;
    u.y = *(unsigned*)&h1;
    return u;
}

// ---------------- prep: init counters ------------------------------------------
__global__ void k_prep() {
    int gtid = blockIdx.x * blockDim.x + threadIdx.x;
    int nthr = gridDim.x * blockDim.x;
    for (int v = gtid; v < N_NODES; v += nthr) { g_ecnt[v] = 0; g_fill[v] = 0; }
}

// ---------------- CSR build ---------------------------------------------------
__global__ void k_count(const int* __restrict__ ei) {
    int e = blockIdx.x * blockDim.x + threadIdx.x;
    if (e < N_EDGES) {
        int d = ei[N_EDGES + e];
        atomicAdd(&g_ecnt[d], 1);
    }
}

__global__ void k_chunksum() {
    __shared__ int sdata[256];
    int c = blockIdx.x, t = threadIdx.x;
    int base = c * CHUNK;
    int s = 0;
    for (int i = t; i < CHUNK; i += 256) {
        int v = base + i;
        s += (v < N_NODES) ? g_ecnt[v] : 0;
    }
    sdata[t] = s;
    __syncthreads();
    for (int off = 128; off > 0; off >>= 1) {
        if (t < off) sdata[t] += sdata[t + off];
        __syncthreads();
    }
    if (t == 0) g_csum[c] = sdata[0];
}

// chunk-local scan + global offset + dinv, all in one kernel (49 blocks x 1024)
__global__ void k_scanfinal() {
    __shared__ int s[CHUNK];
    __shared__ int base;
    int c = blockIdx.x, t = threadIdx.x;
    if (t == 0) {
        int run = 0;
        for (int i = 0; i < c; i++) run += g_csum[i];
        base = run;
    }
    int v = c * CHUNK + t;
    int cnt = (v < N_NODES) ? g_ecnt[v] : 0;
    s[t] = cnt;
    __syncthreads();
    for (int off = 1; off < CHUNK; off <<= 1) {
        int val = (t >= off) ? s[t - off] : 0;
        __syncthreads();
        s[t] += val;
        __syncthreads();
    }
    if (v < N_NODES) {
        g_rowptr[v] = base + s[t] - cnt;           // exclusive
        g_dinv[v]   = rsqrtf((float)(cnt + 1));    // +1 self-loop
    }
    if (c == NCHUNKS - 1 && t == 0) {
        int last = N_NODES - c * CHUNK - 1;
        g_rowptr[N_NODES] = base + s[last];
    }
}

__global__ void k_fill(const int* __restrict__ ei) {
    int e = blockIdx.x * blockDim.x + threadIdx.x;
    if (e < N_EDGES) {
        int sN = ei[e];
        int d  = ei[N_EDGES + e];
        int pos = g_rowptr[d] + atomicAdd(&g_fill[d], 1);
        g_esrc[pos] = sN;
    }
}

// ---------------- GEMM1 (smem-staged, fp16 output) ------------------------------
__global__ void __launch_bounds__(128) k_gemm1(const float* __restrict__ X,
                                               const float* __restrict__ W1) {
    constexpr int K = IN_CH, C = HID_CH, R = 32;
    constexpr int NT  = 128;
    constexpr int CT  = C / 4;      // 32 col-threads
    constexpr int RPT = R / (NT / CT);  // 8 rows per thread

    __shared__ float sx[R * K];

    const int tid  = threadIdx.x;
    const int row0 = blockIdx.x * R;

#pragma unroll
    for (int j = 0; j < (R * K / 4) / NT; j++) {
        int idx  = j * NT + tid;
        int r    = idx / (K / 4);
        int grow = row0 + r;
        float4 v = make_float4(0.f, 0.f, 0.f, 0.f);
        if (grow < N_NODES)
            v = __ldg((const float4*)(X + (size_t)grow * K) + (idx % (K / 4)));
        ((float4*)sx)[idx] = v;
    }
    __syncthreads();

    const int tx    = tid % CT;
    const int col0  = tx * 4;
    const int rbase = (tid / CT) * RPT;

    float acc[RPT][4];
#pragma unroll
    for (int r = 0; r < RPT; r++)
#pragma unroll
        for (int c = 0; c < 4; c++) acc[r][c] = 0.f;

#pragma unroll 2
    for (int kc = 0; kc < K / 4; kc++) {
        const int k = kc * 4;
        float4 w0 = __ldg((const float4*)(W1 + (size_t)(k + 0) * C + col0));
        float4 w1 = __ldg((const float4*)(W1 + (size_t)(k + 1) * C + col0));
        float4 w2 = __ldg((const float4*)(W1 + (size_t)(k + 2) * C + col0));
        float4 w3 = __ldg((const float4*)(W1 + (size_t)(k + 3) * C + col0));
#pragma unroll
        for (int r = 0; r < RPT; r++) {
            float4 xv = *(const float4*)(sx + (rbase + r) * K + k);
            acc[r][0] = fmaf(xv.x, w0.x, acc[r][0]);
            acc[r][1] = fmaf(xv.x, w0.y, acc[r][1]);
            acc[r][2] = fmaf(xv.x, w0.z, acc[r][2]);
            acc[r][3] = fmaf(xv.x, w0.w, acc[r][3]);
            acc[r][0] = fmaf(xv.y, w1.x, acc[r][0]);
            acc[r][1] = fmaf(xv.y, w1.y, acc[r][1]);
            acc[r][2] = fmaf(xv.y, w1.z, acc[r][2]);
            acc[r][3] = fmaf(xv.y, w1.w, acc[r][3]);
            acc[r][0] = fmaf(xv.z, w2.x, acc[r][0]);
            acc[r][1] = fmaf(xv.z, w2.y, acc[r][1]);
            acc[r][2] = fmaf(xv.z, w2.z, acc[r][2]);
            acc[r][3] = fmaf(xv.z, w2.w, acc[r][3]);
            acc[r][0] = fmaf(xv.w, w3.x, acc[r][0]);
            acc[r][1] = fmaf(xv.w, w3.y, acc[r][1]);
            acc[r][2] = fmaf(xv.w, w3.z, acc[r][2]);
            acc[r][3] = fmaf(xv.w, w3.w, acc[r][3]);
        }
    }

#pragma unroll
    for (int r = 0; r < RPT; r++) {
        int row = row0 + rbase + r;
        if (row < N_NODES) {
            uint2 o = float4_to_half4(acc[r][0], acc[r][1], acc[r][2], acc[r][3]);
            *(uint2*)(g_h1 + (size_t)row * C + col0) = o;
        }
    }
}

// ---------------- fused agg1 + gemm2 (fp16 h1 in, fp16 h2 out) ------------------
// Phase 1: 8 warps x 4 nodes aggregate relu(Â h1 + b1) into a 32x128 fp32 smem
//          tile (a1 never hits global). Lane reads 4 halves (8B) per row; a
//          warp covers the whole 256B row.
// Phase 2: h2 = sa @ W2 register-tiled, fp16 output.
__global__ void __launch_bounds__(256) k_agg1gemm2(const float* __restrict__ b1,
                                                   const float* __restrict__ W2) {
    constexpr int RN = 32;                  // nodes per block
    __shared__ float sa[RN * HID_CH];       // 16 KB a1 tile

    const int tid  = threadIdx.x;
    const int w    = tid >> 5;              // warp 0..7
    const int lane = tid & 31;
    const int nbase = blockIdx.x * RN;

    float4 b;
    {
        const float4* b4 = (const float4*)b1;
        b = __ldg(&b4[lane]);
    }

    // ---- phase 1: aggregate 4 nodes per warp ----
#pragma unroll
    for (int i = 0; i < 4; i++) {
        int node = nbase + w * 4 + i;
        float4 r = make_float4(0.f, 0.f, 0.f, 0.f);
        if (node < N_NODES) {
            float dvn = g_dinv[node];
            const uint2* hrow;

            hrow = (const uint2*)(g_h1 + (size_t)node * HID_CH) + lane;
            float4 self = half4_to_float4(__ldcg(hrow));
            float4 a0, a1v;
            a0.x = self.x * dvn; a0.y = self.y * dvn;
            a0.z = self.z * dvn; a0.w = self.w * dvn;
            a1v = make_float4(0.f, 0.f, 0.f, 0.f);

            const int beg = g_rowptr[node];
            const int end = g_rowptr[node + 1];
            int e = beg;
            for (; e + 2 <= end; e += 2) {
                int s0 = __ldg(&g_esrc[e + 0]);
                int s1 = __ldg(&g_esrc[e + 1]);
                float d0 = __ldcg(&g_dinv[s0]);
                float d1 = __ldcg(&g_dinv[s1]);
                uint2 u0 = __ldcg((const uint2*)(g_h1 + (size_t)s0 * HID_CH) + lane);
                uint2 u1 = __ldcg((const uint2*)(g_h1 + (size_t)s1 * HID_CH) + lane);
                float4 v0 = half4_to_float4(u0);
                float4 v1 = half4_to_float4(u1);
                a0.x = fmaf(v0.x, d0, a0.x); a0.y = fmaf(v0.y, d0, a0.y);
                a0.z = fmaf(v0.z, d0, a0.z); a0.w = fmaf(v0.w, d0, a0.w);
                a1v.x = fmaf(v1.x, d1, a1v.x); a1v.y = fmaf(v1.y, d1, a1v.y);
                a1v.z = fmaf(v1.z, d1, a1v.z); a1v.w = fmaf(v1.w, d1, a1v.w);
            }
            if (e < end) {
                int s0 = __ldg(&g_esrc[e]);
                float d0 = __ldcg(&g_dinv[s0]);
                uint2 u0 = __ldcg((const uint2*)(g_h1 + (size_t)s0 * HID_CH) + lane);
                float4 v0 = half4_to_float4(u0);
                a0.x = fmaf(v0.x, d0, a0.x); a0.y = fmaf(v0.y, d0, a0.y);
                a0.z = fmaf(v0.z, d0, a0.z); a0.w = fmaf(v0.w, d0, a0.w);
            }
            a0.x += a1v.x; a0.y += a1v.y; a0.z += a1v.z; a0.w += a1v.w;

            r.x = fmaxf(fmaf(a0.x, dvn, b.x), 0.f);
            r.y = fmaxf(fmaf(a0.y, dvn, b.y), 0.f);
            r.z = fmaxf(fmaf(a0.z, dvn, b.z), 0.f);
            r.w = fmaxf(fmaf(a0.w, dvn, b.w), 0.f);
        }
        *(float4*)(sa + (w * 4 + i) * HID_CH + lane * 4) = r;
    }
    __syncthreads();

    // ---- phase 2: h2[32 x 64] = sa[32 x 128] @ W2[128 x 64] ----
    constexpr int C   = OUT_CH;     // 64
    constexpr int CT  = C / 4;      // 16 col-threads
    constexpr int RPT = 2;
    const int tx    = tid % CT;
    const int col0  = tx * 4;
    const int rbase = (tid / CT) * RPT;

    float acc[RPT][4];
#pragma unroll
    for (int r = 0; r < RPT; r++)
#pragma unroll
        for (int c = 0; c < 4; c++) acc[r][c] = 0.f;

#pragma unroll 2
    for (int kc = 0; kc < HID_CH / 4; kc++) {
        const int k = kc * 4;
        float4 w0 = __ldg((const float4*)(W2 + (size_t)(k + 0) * C + col0));
        float4 w1 = __ldg((const float4*)(W2 + (size_t)(k + 1) * C + col0));
        float4 w2 = __ldg((const float4*)(W2 + (size_t)(k + 2) * C + col0));
        float4 w3 = __ldg((const float4*)(W2 + (size_t)(k + 3) * C + col0));
#pragma unroll
        for (int r = 0; r < RPT; r++) {
            float4 xv = *(const float4*)(sa + (rbase + r) * HID_CH + k);
            acc[r][0] = fmaf(xv.x, w0.x, acc[r][0]);
            acc[r][1] = fmaf(xv.x, w0.y, acc[r][1]);
            acc[r][2] = fmaf(xv.x, w0.z, acc[r][2]);
            acc[r][3] = fmaf(xv.x, w0.w, acc[r][3]);
            acc[r][0] = fmaf(xv.y, w1.x, acc[r][0]);
            acc[r][1] = fmaf(xv.y, w1.y, acc[r][1]);
            acc[r][2] = fmaf(xv.y, w1.z, acc[r][2]);
            acc[r][3] = fmaf(xv.y, w1.w, acc[r][3]);
            acc[r][0] = fmaf(xv.z, w2.x, acc[r][0]);
            acc[r][1] = fmaf(xv.z, w2.y, acc[r][1]);
            acc[r][2] = fmaf(xv.z, w2.z, acc[r][2]);
            acc[r][3] = fmaf(xv.z, w2.w, acc[r][3]);
            acc[r][0] = fmaf(xv.w, w3.x, acc[r][0]);
            acc[r][1] = fmaf(xv.w, w3.y, acc[r][1]);
            acc[r][2] = fmaf(xv.w, w3.z, acc[r][2]);
            acc[r][3] = fmaf(xv.w, w3.w, acc[r][3]);
        }
    }

#pragma unroll
    for (int r = 0; r < RPT; r++) {
        int row = nbase + rbase + r;
        if (row < N_NODES) {
            uint2 o = float4_to_half4(acc[r][0], acc[r][1], acc[r][2], acc[r][3]);
            *(uint2*)(g_h2 + (size_t)row * C + col0) = o;
        }
    }
}

// ---------------- layer-2 aggregation (fp16 h2 in, fp32 out) --------------------
// out[v] = (h2[v]*dinv[v] + sum_s h2[s]*dinv[s]) * dinv[v] + b2
__global__ void k_agg2(const float* __restrict__ b2, float* __restrict__ out) {
    constexpr int F4 = OUT_CH / 4;   // 16 thread-groups, 4 halves (8B) each
    int gtid = blockIdx.x * blockDim.x + threadIdx.x;
    int node = gtid / F4;
    int j    = gtid % F4;
    if (node >= N_NODES) return;

    float dvn = g_dinv[node];

    float4 self = half4_to_float4(__ldcg((const uint2*)(g_h2 + (size_t)node * OUT_CH) + j));
    float4 a0, a1;
    a0.x = self.x * dvn; a0.y = self.y * dvn;
    a0.z = self.z * dvn; a0.w = self.w * dvn;
    a1 = make_float4(0.f, 0.f, 0.f, 0.f);

    const int beg = g_rowptr[node];
    const int end = g_rowptr[node + 1];
    int e = beg;
    for (; e + 2 <= end; e += 2) {
        int s0 = __ldg(&g_esrc[e + 0]);
        int s1 = __ldg(&g_esrc[e + 1]);
        float d0 = __ldcg(&g_dinv[s0]);
        float d1 = __ldcg(&g_dinv[s1]);
        float4 v0 = half4_to_float4(__ldcg((const uint2*)(g_h2 + (size_t)s0 * OUT_CH) + j));
        float4 v1 = half4_to_float4(__ldcg((const uint2*)(g_h2 + (size_t)s1 * OUT_CH) + j));
        a0.x = fmaf(v0.x, d0, a0.x); a0.y = fmaf(v0.y, d0, a0.y);
        a0.z = fmaf(v0.z, d0, a0.z); a0.w = fmaf(v0.w, d0, a0.w);
        a1.x = fmaf(v1.x, d1, a1.x); a1.y = fmaf(v1.y, d1, a1.y);
        a1.z = fmaf(v1.z, d1, a1.z); a1.w = fmaf(v1.w, d1, a1.w);
    }
    if (e < end) {
        int s0 = __ldg(&g_esrc[e]);
        float d0 = __ldcg(&g_dinv[s0]);
        float4 v0 = half4_to_float4(__ldcg((const uint2*)(g_h2 + (size_t)s0 * OUT_CH) + j));
        a0.x = fmaf(v0.x, d0, a0.x); a0.y = fmaf(v0.y, d0, a0.y);
        a0.z = fmaf(v0.z, d0, a0.z); a0.w = fmaf(v0.w, d0, a0.w);
    }
    a0.x += a1.x; a0.y += a1.y; a0.z += a1.z; a0.w += a1.w;

    float4 b = __ldg(&((const float4*)b2)[j]);
    float4 r;
    r.x = fmaf(a0.x, dvn, b.x);
    r.y = fmaf(a0.y, dvn, b.y);
    r.z = fmaf(a0.z, dvn, b.z);
    r.w = fmaf(a0.w, dvn, b.w);
    ((float4*)out)[(size_t)node * F4 + j] = r;
}

// ---------------- launch ------------------------------------------------------
// Fork-join: gemm1 (fma-bound) on the default stream overlaps the CSR build
// (atomic/L2-bound) on a side stream; join before the fused agg1+gemm2.
// Stream/events created per call and leaked (kernel_launch runs ~2x; timed
// replays execute the captured graph). No device memory allocated.
extern "C" void kernel_launch(void* const* d_in, const int* in_sizes, int n_in,
                              void* d_out, int out_size) {
    const float* x  = (const float*)d_in[0];
    const int*   ei = (const int*)d_in[1];
    const float* W1 = (const float*)d_in[2];
    const float* b1 = (const float*)d_in[3];
    const float* W2 = (const float*)d_in[4];
    const float* b2 = (const float*)d_in[5];
    float* out = (float*)d_out;
    (void)in_sizes; (void)n_in; (void)out_size;

    const int TB = 256;
    const int GR = 32;   // rows per block (gemm1 tile / fused tile)

    cudaStream_t s1;
    cudaStreamCreateWithFlags(&s1, cudaStreamNonBlocking);
    cudaEvent_t evA, evB;
    cudaEventCreateWithFlags(&evA, cudaEventDisableTiming);
    cudaEventCreateWithFlags(&evB, cudaEventDisableTiming);

    // fork: side stream joins the (captured) default stream
    cudaEventRecord(evA, 0);
    cudaStreamWaitEvent(s1, evA, 0);

    // side stream: full CSR build (prep -> count -> chunksum -> scan -> fill)
    k_prep     <<<256, TB, 0, s1>>>();
    k_count    <<<(N_EDGES + TB - 1) / TB, TB, 0, s1>>>(ei);
    k_chunksum <<<NCHUNKS, 256, 0, s1>>>();
    k_scanfinal<<<NCHUNKS, CHUNK, 0, s1>>>();
    k_fill     <<<(N_EDGES + TB - 1) / TB, TB, 0, s1>>>(ei);
    cudaEventRecord(evB, s1);

    // default stream: Layer-1 GEMM overlaps the CSR build
    k_gemm1<<<(N_NODES + GR - 1) / GR, 128>>>(x, W1);

    // join, then fused agg1+gemm2 and final aggregation
    cudaStreamWaitEvent(0, evB, 0);
    k_agg1gemm2<<<(N_NODES + GR - 1) / GR, 256>>>(b1, W2);
    k_agg2     <<<N_NODES * (OUT_CH / 4) / TB, TB>>>(b2, out);
}